// round 10
// baseline (speedup 1.0000x reference)
#include <cuda_runtime.h>
#include <cuda_bf16.h>
#include <cstdint>

// ---------------- problem constants ----------------
#define INS   224
#define NH    220
#define NB    48400
#define ICH   16
#define OCH   64
#define KTOT  400
#define XSZ   (ICH*INS*INS)      // 802816

#define OUT_OFF_W   (OCH*NB)
#define OUT_OFF_EXP (OUT_OFF_W + OCH*KTOT)

#define MB    110                // bands (2 image rows each)
#define YROW  49280              // g_yh per-oc size: 220 rows x 224 (pad 4 = 0)

// ---------------- scratch ----------------
__device__ __nv_bfloat16 g_xh[XSZ];
__device__ __nv_bfloat16 g_xl[XSZ];
__device__ __nv_bfloat16 g_xhs[XSZ];         // bf16(x[e+1])
__device__ __nv_bfloat16 g_xls[XSZ];         // lo(x[e+1])
__device__ uint32_t g_xq_h[XSZ];             // pack(hi x[e], hi x[e+220])
__device__ uint32_t g_xq_l[XSZ];
__device__ uint32_t g_xr_h[XSZ];             // pack(hi x[e], hi x[e+49276])
__device__ uint32_t g_xr_l[XSZ];
__device__ __nv_bfloat16 g_Wh[OCH * KTOT];
__device__ __nv_bfloat16 g_Wl[OCH * KTOT];
__device__ __nv_bfloat16 g_yh[OCH * YROW];
__device__ float g_Cpart[MB * 512 * OCH];
__device__ float g_ytypart[MB * OCH * OCH];
__device__ float g_colpart[MB * OCH];
__device__ float g_Cfin[512 * OCH];
__device__ float g_ytyF[OCH * OCH];
__device__ float g_gfp[OCH];

#define MMA16816(c, a0,a1,a2,a3, b0,b1) \
  asm volatile("mma.sync.aligned.m16n8k16.row.col.f32.bf16.bf16.f32 " \
    "{%0,%1,%2,%3},{%4,%5,%6,%7},{%8,%9},{%0,%1,%2,%3};" \
    : "+f"((c)[0]),"+f"((c)[1]),"+f"((c)[2]),"+f"((c)[3]) \
    : "r"(a0),"r"(a1),"r"(a2),"r"(a3),"r"(b0),"r"(b1))

#define LDSM4(r0,r1,r2,r3, saddr) \
  asm volatile("ldmatrix.sync.aligned.m8n8.x4.shared.b16 {%0,%1,%2,%3}, [%4];" \
    : "=r"(r0),"=r"(r1),"=r"(r2),"=r"(r3) : "r"(saddr))

__device__ __forceinline__ uint32_t smem_u32(const void* p) {
    return (uint32_t)__cvta_generic_to_shared(p);
}
__device__ __forceinline__ uint32_t pack_bf2(__nv_bfloat16 lo, __nv_bfloat16 hi) {
    unsigned short a = *(unsigned short*)&lo, b = *(unsigned short*)&hi;
    return (uint32_t)a | ((uint32_t)b << 16);
}

// ======================================================================
// K0a: x -> all bf16 pair arrays
// ======================================================================
__global__ void k_cvt_x(const float* __restrict__ x)
{
    int e = blockIdx.x * 256 + threadIdx.x;
    if (e >= XSZ) return;
    float v = x[e];
    __nv_bfloat16 h = __float2bfloat16(v);
    __nv_bfloat16 l = __float2bfloat16(v - __bfloat162float(h));
    g_xh[e] = h; g_xl[e] = l;

    float v1 = (e + 1 < XSZ) ? x[e + 1] : 0.f;
    __nv_bfloat16 h1 = __float2bfloat16(v1);
    g_xhs[e] = h1;
    g_xls[e] = __float2bfloat16(v1 - __bfloat162float(h1));

    float vq = (e + 220 < XSZ) ? x[e + 220] : 0.f;
    __nv_bfloat16 hq = __float2bfloat16(vq);
    __nv_bfloat16 lq = __float2bfloat16(vq - __bfloat162float(hq));
    g_xq_h[e] = pack_bf2(h, hq);
    g_xq_l[e] = pack_bf2(l, lq);

    float vr = (e + 49276 < XSZ) ? x[e + 49276] : 0.f;
    __nv_bfloat16 hr = __float2bfloat16(vr);
    __nv_bfloat16 lr = __float2bfloat16(vr - __bfloat162float(hr));
    g_xr_h[e] = pack_bf2(h, hr);
    g_xr_l[e] = pack_bf2(l, lr);
}

// ======================================================================
// K0b: W -> bf16 hi/lo ; zero g_yh row pads
// ======================================================================
__global__ void k_cvt_w(const float* __restrict__ W)
{
    int idx = blockIdx.x * 256 + threadIdx.x;
    if (idx < OCH * KTOT) {
        float v = W[idx];
        __nv_bfloat16 h = __float2bfloat16(v);
        g_Wh[idx] = h;
        g_Wl[idx] = __float2bfloat16(v - __bfloat162float(h));
    } else if (idx < OCH * KTOT + OCH * 220 * 2) {
        int p = idx - OCH * KTOT;
        int oc = p / 440, rem = p - oc * 440;
        int r = rem >> 1, half = rem & 1;
        uint32_t* yh32 = (uint32_t*)g_yh;
        yh32[((oc * YROW + r * 224 + 220) >> 1) + half] = 0u;
    }
}

// ======================================================================
// smem A pair-load for conv: pair (kb, kb+1) at local px lpx (+8).
// xeo: [8 q][2 copies][60 u32]; xc: [8 q][120 u32] crossing pairs.
// ======================================================================
__device__ __forceinline__ void loadpairsS(
    int kb, int lpx, int q_lo,
    const uint32_t* xeoH, const uint32_t* xeoL,
    const uint32_t* xcH,  const uint32_t* xcL,
    uint32_t& h0, uint32_t& h1, uint32_t& l0, uint32_t& l1)
{
    int q = kb / 5;
    int kj = kb - q * 5;
    int qr = q - q_lo;
    if (kj == 4) {
        int off = qr * 120 + lpx;
        h0 = xcH[off]; h1 = xcH[off + 8];
        l0 = xcL[off]; l1 = xcL[off + 8];
    } else {
        int cc = lpx + kj;
        int off = qr * 120 + (cc & 1) * 60 + (cc >> 1);
        h0 = xeoH[off]; h1 = xeoH[off + 4];
        l0 = xeoL[off]; l1 = xeoL[off + 4];
    }
}

// ======================================================================
// K1: conv + inhibition, split-bf16 MMA, A staged in smem per s-chunk.
// grid (2, 220), 224 thr (7 warps). Warp = 16 px x 64 oc.
// ======================================================================
#define WPITCH 20

__global__ void __launch_bounds__(224, 4)
k_conv_mma(float* __restrict__ dout)
{
    __shared__ uint32_t wsh[64 * WPITCH];
    __shared__ uint32_t wsl[64 * WPITCH];
    __shared__ uint32_t xeoH[960];    // 8q x (even60 | odd60)
    __shared__ uint32_t xeoL[960];
    __shared__ uint32_t xcH[960];     // 8q x 120 crossing pairs
    __shared__ uint32_t xcL[960];

    const int tid = threadIdx.x;
    const int w = tid >> 5, lane = tid & 31;
    const int g = lane >> 2, t = lane & 3;
    const int h = blockIdx.x;
    const int i = blockIdx.y;
    const int J0 = h * 108;
    const int pxA = (w << 4) + g;

    const int nrow_off = ((lane >> 4) & 1) * 8 + (lane & 7);
    const int k_off = ((lane >> 3) & 1) * 4;
    const uint32_t wsh_s = smem_u32(wsh);
    const uint32_t wsl_s = smem_u32(wsl);
    const uint32_t* wh2g = (const uint32_t*)g_Wh;
    const uint32_t* wl2g = (const uint32_t*)g_Wl;
    const uint32_t* xh32  = (const uint32_t*)g_xh;
    const uint32_t* xl32  = (const uint32_t*)g_xl;
    const uint32_t* xhs32 = (const uint32_t*)g_xhs;
    const uint32_t* xls32 = (const uint32_t*)g_xls;

    float c[8][4];
#pragma unroll
    for (int nt = 0; nt < 8; nt++)
#pragma unroll
        for (int q = 0; q < 4; q++) c[nt][q] = 0.f;

    for (int s = 0; s < 13; s++) {
        __syncthreads();
        const int k0s = s * 32;
        const int q_lo = k0s / 5;
        const int nu = (s < 12) ? 16 : 8;
        // ---- W chunk ----
        for (int idx = tid; idx < 64 * nu; idx += 224) {
            int row = idx / nu, u = idx - row * nu;
            wsh[row * WPITCH + u] = wh2g[row * 200 + (k0s >> 1) + u];
            wsl[row * WPITCH + u] = wl2g[row * 200 + (k0s >> 1) + u];
        }
        // ---- A even/odd copies: straight u32 copies of g_x{h,l}{,s} ----
        for (int idx = tid; idx < 1920; idx += 224) {
            int arr = idx / 960;
            int r = idx - arr * 960;
            int qr = r / 120;
            int rr = r - qr * 120;
            int cpy = rr / 60;
            int u = rr - cpy * 60;
            int q = q_lo + qr;
            uint32_t v = 0u;
            if (u < 58 && q < 80) {
                int ic5 = q / 5;
                int b = ic5 * 25088 + (q - ic5 * 5 + i) * 112 + 54 * h + u;
                v = arr ? (cpy ? xls32[b] : xl32[b])
                        : (cpy ? xhs32[b] : xh32[b]);
            }
            (arr ? xeoL : xeoH)[qr * 120 + cpy * 60 + u] = v;
        }
        // ---- A crossing pairs from g_xq/g_xr ----
        for (int idx = tid; idx < 1920; idx += 224) {
            int arr = idx / 960;
            int r = idx - arr * 960;
            int qr = r / 120;
            int u = r - qr * 120;
            int q = q_lo + qr;
            uint32_t v = 0u;
            if (u < 112 && q < 79) {
                int ic5 = q / 5, ki = q - ic5 * 5;
                int e = ic5 * 50176 + (ki + i) * 224 + J0 + u + 4;
                v = (ki == 4) ? (arr ? g_xr_l[e] : g_xr_h[e])
                              : (arr ? g_xq_l[e] : g_xq_h[e]);
            }
            (arr ? xcL : xcH)[qr * 120 + u] = v;
        }
        __syncthreads();

        const int nks = (s < 12) ? 2 : 1;
        for (int ksl = 0; ksl < nks; ksl++) {
            const int kb0 = k0s + ksl * 16 + 2 * t;
            uint32_t ah0, ah1, al0, al1, ah2, ah3, al2, al3;
            loadpairsS(kb0,     pxA, q_lo, xeoH, xeoL, xcH, xcL, ah0, ah1, al0, al1);
            loadpairsS(kb0 + 8, pxA, q_lo, xeoH, xeoL, xcH, xcL, ah2, ah3, al2, al3);

            const uint32_t wbase = ((uint32_t)(nrow_off * WPITCH + ksl * 8 + k_off)) * 4;
#pragma unroll
            for (int p = 0; p < 4; p++) {
                uint32_t bh0, bh1, bh2, bh3, bl0, bl1, bl2, bl3;
                const uint32_t off = wbase + (uint32_t)(p * 16 * WPITCH) * 4;
                LDSM4(bh0, bh1, bh2, bh3, wsh_s + off);
                LDSM4(bl0, bl1, bl2, bl3, wsl_s + off);
                MMA16816(c[2 * p],     ah0, ah1, ah2, ah3, bh0, bh1);
                MMA16816(c[2 * p],     al0, al1, al2, al3, bh0, bh1);
                MMA16816(c[2 * p],     ah0, ah1, ah2, ah3, bl0, bl1);
                MMA16816(c[2 * p + 1], ah0, ah1, ah2, ah3, bh2, bh3);
                MMA16816(c[2 * p + 1], al0, al1, al2, al3, bh2, bh3);
                MMA16816(c[2 * p + 1], ah0, ah1, ah2, ah3, bl2, bl3);
            }
        }
    }

    // ---- inhibition + writeback ----
    float m0 = 0.f, m1 = 0.f;
#pragma unroll
    for (int nt = 0; nt < 8; nt++) {
        m0 = fmaxf(m0, fmaxf(c[nt][0], c[nt][1]));
        m1 = fmaxf(m1, fmaxf(c[nt][2], c[nt][3]));
    }
    m0 = fmaxf(m0, __shfl_xor_sync(0xFFFFFFFFu, m0, 1));
    m0 = fmaxf(m0, __shfl_xor_sync(0xFFFFFFFFu, m0, 2));
    m1 = fmaxf(m1, __shfl_xor_sync(0xFFFFFFFFu, m1, 1));
    m1 = fmaxf(m1, __shfl_xor_sync(0xFFFFFFFFu, m1, 2));
    const float inv0 = 1.f / (m0 + 1e-9f);
    const float inv1 = 1.f / (m1 + 1e-9f);

    const int pxg = i * NH + J0 + pxA;
    const int pyg = i * 224 + J0 + pxA;
#pragma unroll
    for (int nt = 0; nt < 8; nt++) {
        const int oc = nt * 8 + 2 * t;
        float v;
        v = fmaxf(c[nt][0], 0.f) * inv0; v = (v * v) * (v * v) * v;
        dout[(size_t)oc * NB + pxg] = v;
        g_yh[(size_t)oc * YROW + pyg] = __float2bfloat16(v);
        v = fmaxf(c[nt][1], 0.f) * inv0; v = (v * v) * (v * v) * v;
        dout[(size_t)(oc + 1) * NB + pxg] = v;
        g_yh[(size_t)(oc + 1) * YROW + pyg] = __float2bfloat16(v);
        v = fmaxf(c[nt][2], 0.f) * inv1; v = (v * v) * (v * v) * v;
        dout[(size_t)oc * NB + pxg + 8] = v;
        g_yh[(size_t)oc * YROW + pyg + 8] = __float2bfloat16(v);
        v = fmaxf(c[nt][3], 0.f) * inv1; v = (v * v) * (v * v) * v;
        dout[(size_t)(oc + 1) * NB + pxg + 8] = v;
        g_yh[(size_t)(oc + 1) * YROW + pyg + 8] = __float2bfloat16(v);
    }
}

// ======================================================================
// K2: fused Hebbian GEMMs. grid (110, 5), 256 thr, 55.7KB dyn smem.
//   kt 0..3 : y^T @ xf  (A smem even/odd slabs, B smem+LDSM)
//   kt == 4 : y^T @ y + colsums (frag-direct global)
// ======================================================================
#define BPITCH 116
#define NQ     28                 // q-row slabs per kt
#define ASZ    (NQ * 232)         // 6496 u32
#define BSZ    (64 * BPITCH)      // 7424 u32

extern __shared__ uint32_t s_dyn[];

__global__ void __launch_bounds__(256, 4)
k_hebb_mma()
{
    const int tid  = threadIdx.x;
    const int band = blockIdx.x;
    const int kt   = blockIdx.y;
    const int w    = tid >> 5;
    const int lane = tid & 31;
    const int g    = lane >> 2;
    const int t    = lane & 3;

    const uint32_t* yh32 = (const uint32_t*)g_yh;

    if (kt < 4) {
        // ---------------- y^T @ xf ----------------
        uint32_t* As = s_dyn;
        uint32_t* Bs = s_dyn + ASZ;
        const uint32_t* xh32  = (const uint32_t*)g_xh;
        const uint32_t* xhs32 = (const uint32_t*)g_xhs;
        const int q_lo = (kt * 128) / 5;

        int rA = kt * 128 + w * 16 + g;
        int q0 = rA / 5, kj0 = rA - q0 * 5;
        int baseA0 = (q0 - q_lo) * 232 + (kj0 & 1) * 116 + (kj0 >> 1);
        int rB = rA + 8;
        int q1 = rB / 5, kj1 = rB - q1 * 5;
        int baseA1 = (q1 - q_lo) * 232 + (kj1 & 1) * 116 + (kj1 >> 1);

        const uint32_t bsm = smem_u32(Bs);
        const int nrow_off = ((lane >> 4) & 1) * 8 + (lane & 7);
        const int k_off = ((lane >> 3) & 1) * 4;

        float c[8][4];
#pragma unroll
        for (int n = 0; n < 8; n++)
#pragma unroll
            for (int q = 0; q < 4; q++) c[n][q] = 0.f;

#pragma unroll
        for (int b2 = 0; b2 < 2; b2++) {
            const int ir = band * 2 + b2;
            __syncthreads();
            // ---- A slabs: even/odd u32 copies of x rows ----
            for (int idx = tid; idx < ASZ; idx += 256) {
                int qr = idx / 232;
                int r = idx - qr * 232;
                int cpy = r / 116;
                int u = r - cpy * 116;
                int q = q_lo + qr;
                uint32_t v = 0u;
                if (u < 112 && q < 80) {
                    int ic5 = q / 5;
                    int b = ic5 * 25088 + (q - ic5 * 5 + ir) * 112 + u;
                    v = cpy ? xhs32[b] : xh32[b];
                }
                As[idx] = v;
            }
            // ---- B tile ----
            for (int idx = tid; idx < 64 * 128; idx += 256) {
                int row = idx >> 7, pc = idx & 127;
                if (pc < 112) {
                    uint32_t v = 0;
                    if (pc < 110)
                        v = yh32[((row * YROW + ir * 224) >> 1) + pc];
                    Bs[row * BPITCH + pc] = v;
                }
            }
            __syncthreads();

#pragma unroll
            for (int ks = 0; ks < 14; ks++) {
                uint32_t a0 = As[baseA0 + ks * 8 + t];
                uint32_t a2 = As[baseA0 + ks * 8 + t + 4];
                uint32_t a1 = As[baseA1 + ks * 8 + t];
                uint32_t a3 = As[baseA1 + ks * 8 + t + 4];
#pragma unroll
                for (int p = 0; p < 4; p++) {
                    uint32_t b0, b1, b2r, b3;
                    uint32_t addr = bsm + (uint32_t)((p * 16 + nrow_off) * BPITCH +
                                                     ks * 8 + k_off) * 4;
                    LDSM4(b0, b1, b2r, b3, addr);
                    MMA16816(c[2 * p],     a0, a1, a2, a3, b0, b1);
                    MMA16816(c[2 * p + 1], a0, a1, a2, a3, b2r, b3);
                }
            }
        }

        float* dst = g_Cpart + ((size_t)band * 512 + kt * 128 + w * 16) * 64;
#pragma unroll
        for (int nt = 0; nt < 8; nt++) {
            *(float2*)&dst[(g)     * 64 + nt * 8 + 2 * t] = make_float2(c[nt][0], c[nt][1]);
            *(float2*)&dst[(g + 8) * 64 + nt * 8 + 2 * t] = make_float2(c[nt][2], c[nt][3]);
        }
    } else {
        // ---------------- y^T @ y + colsums ----------------
        const int m0 = (w & 3) * 16;
        const int n0 = (w >> 2) * 32;

        float c[4][4];
#pragma unroll
        for (int n = 0; n < 4; n++)
#pragma unroll
            for (int q = 0; q < 4; q++) c[n][q] = 0.f;

#pragma unroll
        for (int b2 = 0; b2 < 2; b2++) {
            const int ir = band * 2 + b2;
            const uint32_t rowoff = (uint32_t)(ir * 112);
            const uint32_t baA = (uint32_t)((m0 + g) * YROW >> 1) + rowoff;
            const uint32_t baB = (uint32_t)((m0 + g + 8) * YROW >> 1) + rowoff;
#pragma unroll 2
            for (int ks = 0; ks < 14; ks++) {
                uint32_t a0 = yh32[baA + ks * 8 + t];
                uint32_t a2 = yh32[baA + ks * 8 + t + 4];
                uint32_t a1 = yh32[baB + ks * 8 + t];
                uint32_t a3 = yh32[baB + ks * 8 + t + 4];
#pragma unroll
                for (int nt = 0; nt < 4; nt++) {
                    const int n = n0 + nt * 8 + g;
                    uint32_t bb = (uint32_t)(n * YROW >> 1) + rowoff;
                    uint32_t b0 = yh32[bb + ks * 8 + t];
                    uint32_t b1 = yh32[bb + ks * 8 + t + 4];
                    MMA16816(c[nt], a0, a1, a2, a3, b0, b1);
                }
            }
        }

        float* dst = g_ytypart + (size_t)band * 4096;
#pragma unroll
        for (int nt = 0; nt < 4; nt++) {
            const int col = n0 + nt * 8 + 2 * t;
            *(float2*)&dst[(m0 + g) * 64 + col]     = make_float2(c[nt][0], c[nt][1]);
            *(float2*)&dst[(m0 + g + 8) * 64 + col] = make_float2(c[nt][2], c[nt][3]);
        }

        {
            const int oc = tid >> 2, q = tid & 3;
            float s = 0.f;
#pragma unroll
            for (int b2 = 0; b2 < 2; b2++) {
                const uint32_t base = (uint32_t)(oc * YROW >> 1) +
                                      (uint32_t)((band * 2 + b2) * 112) + q * 28;
#pragma unroll 7
                for (int k = 0; k < 28; k++) {
                    uint32_t v = yh32[base + k];
                    __nv_bfloat162 hh = *(__nv_bfloat162*)&v;
                    float2 f = __bfloat1622float2(hh);
                    s += f.x + f.y;
                }
            }
            s += __shfl_xor_sync(0xFFFFFFFFu, s, 1);
            s += __shfl_xor_sync(0xFFFFFFFFu, s, 2);
            if (q == 0) g_colpart[band * OCH + oc] = s;
        }
    }
}

// ======================================================================
// K3: reduce partials + exp_new/gfp. grid 37 x 256.
// ======================================================================
__global__ void k_reduce(const float* __restrict__ exp_avg,
                         float* __restrict__ dout)
{
    int e = blockIdx.x * 256 + threadIdx.x;
    if (e < 8192) {
        const float4* P = (const float4*)g_Cpart;
        float4 s = make_float4(0.f, 0.f, 0.f, 0.f);
#pragma unroll 2
        for (int b = 0; b < MB; b++) {
            float4 v = P[(size_t)b * 8192 + e];
            s.x += v.x; s.y += v.y; s.z += v.z; s.w += v.w;
        }
        ((float4*)g_Cfin)[e] = s;
    } else if (e < 9216) {
        int i = e - 8192;
        const float4* P = (const float4*)g_ytypart;
        float4 s = make_float4(0.f, 0.f, 0.f, 0.f);
#pragma unroll 2
        for (int b = 0; b < MB; b++) {
            float4 v = P[(size_t)b * 1024 + i];
            s.x += v.x; s.y += v.y; s.z += v.z; s.w += v.w;
        }
        ((float4*)g_ytyF)[i] = s;
    }

    if (blockIdx.x == 36) {
        __shared__ float sh[OCH];
        int t = threadIdx.x;
        if (t < OCH) {
            float cs = 0.f;
#pragma unroll 10
            for (int b = 0; b < MB; b++) cs += g_colpart[b * OCH + t];
            float en = 0.99f * exp_avg[t] + (1.0f - 0.99f) * (cs / (float)NB);
            sh[t] = en;
            dout[OUT_OFF_EXP + t] = en;
        }
        __syncthreads();
        if (t < OCH) {
            float s = 0.f;
            for (int i = 0; i < OCH; i++) s += sh[i];
            float A = sh[t] / (s * (1.0f / (float)OCH));
            g_gfp[t] = 0.01f * tanhf(-0.01f * (A - 1.0f)) + 1.0f;
        }
    }
}

// ======================================================================
// K4: weight update.
// ======================================================================
__global__ void k_wupd(const float* __restrict__ W, float* __restrict__ dout)
{
    int idx = blockIdx.x * 256 + threadIdx.x;
    if (idx >= OCH * KTOT) return;
    int oc = idx / KTOT;
    int k = idx - oc * KTOT;
    float dot = 0.f;
#pragma unroll 8
    for (int b = 0; b < OCH; b++)
        dot += g_ytyF[oc * OCH + b] * W[b * KTOT + k];
    const float LRN = (float)(0.005 / 48400.0);
    float d = LRN * (g_Cfin[k * 64 + oc] - dot);
    float wn = fmaxf(W[idx] + d, 0.f);
    dout[OUT_OFF_W + idx] = wn * g_gfp[oc];
}

// ======================================================================
extern "C" void kernel_launch(void* const* d_in, const int* in_sizes, int n_in,
                              void* d_out, int out_size)
{
    const float* x  = (const float*)d_in[0];
    const float* W  = (const float*)d_in[1];
    const float* ea = (const float*)d_in[2];
    float* dout = (float*)d_out;

    const int hebb_smem = (ASZ + BSZ) * 4;   // 55680 B
    cudaFuncSetAttribute(k_hebb_mma,
                         cudaFuncAttributeMaxDynamicSharedMemorySize, hebb_smem);

    k_cvt_x<<<(XSZ + 255) / 256, 256>>>(x);
    k_cvt_w<<<(OCH * KTOT + OCH * 440 + 255) / 256, 256>>>(W);
    dim3 g1(2, 220);
    k_conv_mma<<<g1, 224>>>(dout);
    dim3 g2(MB, 5);
    k_hebb_mma<<<g2, 256, hebb_smem>>>();
    k_reduce<<<37, 256>>>(ea, dout);
    k_wupd<<<100, 256>>>(W, dout);
}

// round 11
// speedup vs baseline: 1.3130x; 1.3130x over previous
#include <cuda_runtime.h>
#include <cuda_bf16.h>
#include <cstdint>

// ---------------- problem constants ----------------
#define INS   224
#define NH    220
#define NB    48400
#define ICH   16
#define OCH   64
#define KTOT  400
#define XSZ   (ICH*INS*INS)      // 802816

#define OUT_OFF_W   (OCH*NB)
#define OUT_OFF_EXP (OUT_OFF_W + OCH*KTOT)

#define MB    110                // bands (2 image rows each)
#define YROW  49280              // g_yh per-oc size: 220 rows x 224 (pad 4 = 0)

// ---------------- scratch ----------------
__device__ __nv_bfloat16 g_xh[XSZ];
__device__ __nv_bfloat16 g_xl[XSZ];
__device__ __nv_bfloat16 g_xhs[XSZ];         // bf16(x[e+1])
__device__ __nv_bfloat16 g_xls[XSZ];         // lo(x[e+1])
__device__ uint32_t g_xq_h[XSZ];             // pack(hi x[e], hi x[e+220])
__device__ uint32_t g_xq_l[XSZ];
__device__ uint32_t g_xr_h[XSZ];             // pack(hi x[e], hi x[e+49276])
__device__ uint32_t g_xr_l[XSZ];
__device__ __nv_bfloat16 g_Wh[OCH * KTOT];
__device__ __nv_bfloat16 g_Wl[OCH * KTOT];
__device__ __nv_bfloat16 g_yh[OCH * YROW];
__device__ float g_Cpart[MB * 512 * OCH];
__device__ float g_ytypart[MB * OCH * OCH];
__device__ float g_colpart[MB * OCH];
__device__ float g_Cfin[512 * OCH];
__device__ float g_ytyF[OCH * OCH];
__device__ float g_gfp[OCH];

#define MMA16816(c, a0,a1,a2,a3, b0,b1) \
  asm volatile("mma.sync.aligned.m16n8k16.row.col.f32.bf16.bf16.f32 " \
    "{%0,%1,%2,%3},{%4,%5,%6,%7},{%8,%9},{%0,%1,%2,%3};" \
    : "+f"((c)[0]),"+f"((c)[1]),"+f"((c)[2]),"+f"((c)[3]) \
    : "r"(a0),"r"(a1),"r"(a2),"r"(a3),"r"(b0),"r"(b1))

#define LDSM4(r0,r1,r2,r3, saddr) \
  asm volatile("ldmatrix.sync.aligned.m8n8.x4.shared.b16 {%0,%1,%2,%3}, [%4];" \
    : "=r"(r0),"=r"(r1),"=r"(r2),"=r"(r3) : "r"(saddr))

__device__ __forceinline__ uint32_t smem_u32(const void* p) {
    return (uint32_t)__cvta_generic_to_shared(p);
}
__device__ __forceinline__ uint32_t pack_bf2(__nv_bfloat16 lo, __nv_bfloat16 hi) {
    unsigned short a = *(unsigned short*)&lo, b = *(unsigned short*)&hi;
    return (uint32_t)a | ((uint32_t)b << 16);
}

// ======================================================================
// K0a: x -> all bf16 pair arrays
// ======================================================================
__global__ void k_cvt_x(const float* __restrict__ x)
{
    int e = blockIdx.x * 256 + threadIdx.x;
    if (e >= XSZ) return;
    float v = x[e];
    __nv_bfloat16 h = __float2bfloat16(v);
    __nv_bfloat16 l = __float2bfloat16(v - __bfloat162float(h));
    g_xh[e] = h; g_xl[e] = l;

    float v1 = (e + 1 < XSZ) ? x[e + 1] : 0.f;
    __nv_bfloat16 h1 = __float2bfloat16(v1);
    g_xhs[e] = h1;
    g_xls[e] = __float2bfloat16(v1 - __bfloat162float(h1));

    float vq = (e + 220 < XSZ) ? x[e + 220] : 0.f;
    __nv_bfloat16 hq = __float2bfloat16(vq);
    __nv_bfloat16 lq = __float2bfloat16(vq - __bfloat162float(hq));
    g_xq_h[e] = pack_bf2(h, hq);
    g_xq_l[e] = pack_bf2(l, lq);

    float vr = (e + 49276 < XSZ) ? x[e + 49276] : 0.f;
    __nv_bfloat16 hr = __float2bfloat16(vr);
    __nv_bfloat16 lr = __float2bfloat16(vr - __bfloat162float(hr));
    g_xr_h[e] = pack_bf2(h, hr);
    g_xr_l[e] = pack_bf2(l, lr);
}

// ======================================================================
// K0b: W -> bf16 hi/lo ; zero g_yh row pads
// ======================================================================
__global__ void k_cvt_w(const float* __restrict__ W)
{
    int idx = blockIdx.x * 256 + threadIdx.x;
    if (idx < OCH * KTOT) {
        float v = W[idx];
        __nv_bfloat16 h = __float2bfloat16(v);
        g_Wh[idx] = h;
        g_Wl[idx] = __float2bfloat16(v - __bfloat162float(h));
    } else if (idx < OCH * KTOT + OCH * 220 * 2) {
        int p = idx - OCH * KTOT;
        int oc = p / 440, rem = p - oc * 440;
        int r = rem >> 1, half = rem & 1;
        uint32_t* yh32 = (uint32_t*)g_yh;
        yh32[((oc * YROW + r * 224 + 220) >> 1) + half] = 0u;
    }
}

// ======================================================================
// A pair-load for conv: element pair (kb, kb+1) at pixel column eb(+8).
// ======================================================================
__device__ __forceinline__ void loadpairs(int kb, int eb, int pxA,
    uint32_t& h0, uint32_t& h1, uint32_t& l0, uint32_t& l1)
{
    int q = kb / 5;
    int kj = kb - q * 5;
    int ic = q / 5;
    int e = q * 224 + ic * 49056 + eb + kj;
    if (kj == 4) {
        bool icx = (q - ic * 5) == 4;
        const uint32_t* ph = icx ? g_xr_h : g_xq_h;
        const uint32_t* pl = icx ? g_xr_l : g_xq_l;
        h0 = ph[e]; h1 = ph[e + 8];
        l0 = pl[e]; l1 = pl[e + 8];
    } else {
        int par = (pxA + kj) & 1;
        const uint32_t* ph = par ? (const uint32_t*)g_xhs : (const uint32_t*)g_xh;
        const uint32_t* pl = par ? (const uint32_t*)g_xls : (const uint32_t*)g_xl;
        int w0 = e >> 1;
        h0 = ph[w0]; h1 = ph[w0 + 4];
        l0 = pl[w0]; l1 = pl[w0 + 4];
    }
}

// ======================================================================
// K1: conv + inhibition, split-bf16 MMA, A direct-global (prefetched),
// W via LDSM. grid (2, 220), 224 thr (7 warps). Warp = 16 px x 64 oc.
// ======================================================================
#define WPITCH 20

__global__ void __launch_bounds__(224)
k_conv_mma(float* __restrict__ dout)
{
    __shared__ uint32_t wsh[64 * WPITCH];
    __shared__ uint32_t wsl[64 * WPITCH];

    const int tid = threadIdx.x;
    const int w = tid >> 5, lane = tid & 31;
    const int g = lane >> 2, t = lane & 3;
    const int h = blockIdx.x;
    const int i = blockIdx.y;
    const int J0 = h * 108;
    const int pxA = (w << 4) + g;
    const int eb = i * 224 + J0 + pxA;

    const int nrow_off = ((lane >> 4) & 1) * 8 + (lane & 7);
    const int k_off = ((lane >> 3) & 1) * 4;
    const uint32_t wsh_s = smem_u32(wsh);
    const uint32_t wsl_s = smem_u32(wsl);
    const uint32_t* wh2g = (const uint32_t*)g_Wh;
    const uint32_t* wl2g = (const uint32_t*)g_Wl;

    float c[8][4];
#pragma unroll
    for (int nt = 0; nt < 8; nt++)
#pragma unroll
        for (int q = 0; q < 4; q++) c[nt][q] = 0.f;

    for (int s = 0; s < 13; s++) {
        __syncthreads();
        const int k0s = s * 32;
        const int nu = (s < 12) ? 16 : 8;
        for (int idx = tid; idx < 64 * nu; idx += 224) {
            int row = idx / nu, u = idx - row * nu;
            wsh[row * WPITCH + u] = wh2g[row * 200 + (k0s >> 1) + u];
            wsl[row * WPITCH + u] = wl2g[row * 200 + (k0s >> 1) + u];
        }
        __syncthreads();

        const int nks = (s < 12) ? 2 : 1;
        // ---- prefetch ALL A pairs for this chunk (up to 16 LDG in flight) ----
        uint32_t A[2][8];
        {
            const int kb0 = k0s + 2 * t;
            loadpairs(kb0,     eb, pxA, A[0][0], A[0][1], A[0][4], A[0][5]);
            loadpairs(kb0 + 8, eb, pxA, A[0][2], A[0][3], A[0][6], A[0][7]);
        }
        if (nks == 2) {
            const int kb1 = k0s + 16 + 2 * t;
            loadpairs(kb1,     eb, pxA, A[1][0], A[1][1], A[1][4], A[1][5]);
            loadpairs(kb1 + 8, eb, pxA, A[1][2], A[1][3], A[1][6], A[1][7]);
        }

        for (int ksl = 0; ksl < nks; ksl++) {
            const uint32_t ah0 = A[ksl][0], ah1 = A[ksl][1];
            const uint32_t ah2 = A[ksl][2], ah3 = A[ksl][3];
            const uint32_t al0 = A[ksl][4], al1 = A[ksl][5];
            const uint32_t al2 = A[ksl][6], al3 = A[ksl][7];

            const uint32_t wbase = ((uint32_t)(nrow_off * WPITCH + ksl * 8 + k_off)) * 4;
#pragma unroll
            for (int p = 0; p < 4; p++) {
                uint32_t bh0, bh1, bh2, bh3, bl0, bl1, bl2, bl3;
                const uint32_t off = wbase + (uint32_t)(p * 16 * WPITCH) * 4;
                LDSM4(bh0, bh1, bh2, bh3, wsh_s + off);
                LDSM4(bl0, bl1, bl2, bl3, wsl_s + off);
                MMA16816(c[2 * p],     ah0, ah1, ah2, ah3, bh0, bh1);
                MMA16816(c[2 * p],     al0, al1, al2, al3, bh0, bh1);
                MMA16816(c[2 * p],     ah0, ah1, ah2, ah3, bl0, bl1);
                MMA16816(c[2 * p + 1], ah0, ah1, ah2, ah3, bh2, bh3);
                MMA16816(c[2 * p + 1], al0, al1, al2, al3, bh2, bh3);
                MMA16816(c[2 * p + 1], ah0, ah1, ah2, ah3, bl2, bl3);
            }
        }
    }

    // ---- inhibition + writeback ----
    float m0 = 0.f, m1 = 0.f;
#pragma unroll
    for (int nt = 0; nt < 8; nt++) {
        m0 = fmaxf(m0, fmaxf(c[nt][0], c[nt][1]));
        m1 = fmaxf(m1, fmaxf(c[nt][2], c[nt][3]));
    }
    m0 = fmaxf(m0, __shfl_xor_sync(0xFFFFFFFFu, m0, 1));
    m0 = fmaxf(m0, __shfl_xor_sync(0xFFFFFFFFu, m0, 2));
    m1 = fmaxf(m1, __shfl_xor_sync(0xFFFFFFFFu, m1, 1));
    m1 = fmaxf(m1, __shfl_xor_sync(0xFFFFFFFFu, m1, 2));
    const float inv0 = 1.f / (m0 + 1e-9f);
    const float inv1 = 1.f / (m1 + 1e-9f);

    const int pxg = i * NH + J0 + pxA;
    const int pyg = i * 224 + J0 + pxA;
#pragma unroll
    for (int nt = 0; nt < 8; nt++) {
        const int oc = nt * 8 + 2 * t;
        float v;
        v = fmaxf(c[nt][0], 0.f) * inv0; v = (v * v) * (v * v) * v;
        dout[(size_t)oc * NB + pxg] = v;
        g_yh[(size_t)oc * YROW + pyg] = __float2bfloat16(v);
        v = fmaxf(c[nt][1], 0.f) * inv0; v = (v * v) * (v * v) * v;
        dout[(size_t)(oc + 1) * NB + pxg] = v;
        g_yh[(size_t)(oc + 1) * YROW + pyg] = __float2bfloat16(v);
        v = fmaxf(c[nt][2], 0.f) * inv1; v = (v * v) * (v * v) * v;
        dout[(size_t)oc * NB + pxg + 8] = v;
        g_yh[(size_t)oc * YROW + pyg + 8] = __float2bfloat16(v);
        v = fmaxf(c[nt][3], 0.f) * inv1; v = (v * v) * (v * v) * v;
        dout[(size_t)(oc + 1) * NB + pxg + 8] = v;
        g_yh[(size_t)(oc + 1) * YROW + pyg + 8] = __float2bfloat16(v);
    }
}

// ======================================================================
// K2: fused Hebbian GEMMs. grid (110, 5), 256 thr, 58KB dyn smem.
//   kt 0..3 : y^T @ xf  (A direct-global with 4-deep prefetch,
//                        B 2-band smem + LDSM)
//   kt == 4 : y^T @ y + colsums (frag-direct global)
// ======================================================================
#define BPITCH 116
#define BSZ1   (64 * BPITCH)       // 7424 u32 per band

extern __shared__ uint32_t s_B2[];

__global__ void __launch_bounds__(256)
k_hebb_mma()
{
    const int tid  = threadIdx.x;
    const int band = blockIdx.x;
    const int kt   = blockIdx.y;
    const int w    = tid >> 5;
    const int lane = tid & 31;
    const int g    = lane >> 2;
    const int t    = lane & 3;

    const uint32_t* yh32 = (const uint32_t*)g_yh;

    if (kt < 4) {
        // ---------------- y^T @ xf ----------------
        const uint32_t* xh32  = (const uint32_t*)g_xh;
        const uint32_t* xhs32 = (const uint32_t*)g_xhs;

        // fill B for BOTH band rows
        for (int idx = tid; idx < 2 * 64 * 128; idx += 256) {
            int b2 = idx >> 13;
            int row = (idx >> 7) & 63;
            int pc = idx & 127;
            if (pc < 112) {
                uint32_t v = 0;
                if (pc < 110)
                    v = yh32[((row * YROW + (band * 2 + b2) * 224) >> 1) + pc];
                s_B2[b2 * BSZ1 + row * BPITCH + pc] = v;
            }
        }

        int rA = kt * 128 + w * 16 + g;
        int rB = rA + 8;
        int rc0 = 0, rc1 = 0;
        const uint32_t *p0 = xh32, *p1 = xh32;
        if (rA < KTOT) {
            int ic = rA / 25, rem = rA - ic * 25;
            int ki = rem / 5, kj = rem - ki * 5;
            rc0 = ic * 50176 + ki * 224 + kj;
            if (kj & 1) p0 = xhs32;
        }
        if (rB < KTOT) {
            int ic = rB / 25, rem = rB - ic * 25;
            int ki = rem / 5, kj = rem - ki * 5;
            rc1 = ic * 50176 + ki * 224 + kj;
            if (kj & 1) p1 = xhs32;
        }
        uint32_t base0[2], base1[2];
#pragma unroll
        for (int b2 = 0; b2 < 2; b2++) {
            const int ir = band * 2 + b2;
            base0[b2] = (uint32_t)(rc0 + ir * 224) >> 1;
            base1[b2] = (uint32_t)(rc1 + ir * 224) >> 1;
        }

        const uint32_t bsm = smem_u32(s_B2);
        const int nrow_off = ((lane >> 4) & 1) * 8 + (lane & 7);
        const int k_off = ((lane >> 3) & 1) * 4;

        float c[8][4];
#pragma unroll
        for (int n = 0; n < 8; n++)
#pragma unroll
            for (int q = 0; q < 4; q++) c[n][q] = 0.f;

        // 4-deep A prefetch pipeline over flat ks2 = b2*14 + ks
        uint32_t buf[4][4];
#pragma unroll
        for (int i = 0; i < 4; i++) {
            buf[i][0] = p0[base0[0] + i * 8 + t];
            buf[i][2] = p0[base0[0] + i * 8 + t + 4];
            buf[i][1] = p1[base1[0] + i * 8 + t];
            buf[i][3] = p1[base1[0] + i * 8 + t + 4];
        }

        __syncthreads();   // B ready

#pragma unroll
        for (int ks2 = 0; ks2 < 28; ks2++) {
            const int cur = ks2 & 3;
            const uint32_t a0 = buf[cur][0], a1 = buf[cur][1];
            const uint32_t a2 = buf[cur][2], a3 = buf[cur][3];
            if (ks2 + 4 < 28) {
                const int nx = ks2 + 4;
                const int nb2 = (nx >= 14) ? 1 : 0;
                const int nks = nx - 14 * nb2;
                buf[cur][0] = p0[base0[nb2] + nks * 8 + t];
                buf[cur][2] = p0[base0[nb2] + nks * 8 + t + 4];
                buf[cur][1] = p1[base1[nb2] + nks * 8 + t];
                buf[cur][3] = p1[base1[nb2] + nks * 8 + t + 4];
            }
            const int b2 = (ks2 >= 14) ? 1 : 0;
            const int ks = ks2 - 14 * b2;
            const uint32_t bb = bsm + (uint32_t)(b2 * BSZ1) * 4;
#pragma unroll
            for (int p = 0; p < 4; p++) {
                uint32_t b0, b1, b2r, b3;
                uint32_t addr = bb + (uint32_t)((p * 16 + nrow_off) * BPITCH +
                                                ks * 8 + k_off) * 4;
                LDSM4(b0, b1, b2r, b3, addr);
                MMA16816(c[2 * p],     a0, a1, a2, a3, b0, b1);
                MMA16816(c[2 * p + 1], a0, a1, a2, a3, b2r, b3);
            }
        }

        float* dst = g_Cpart + ((size_t)band * 512 + kt * 128 + w * 16) * 64;
#pragma unroll
        for (int nt = 0; nt < 8; nt++) {
            *(float2*)&dst[(g)     * 64 + nt * 8 + 2 * t] = make_float2(c[nt][0], c[nt][1]);
            *(float2*)&dst[(g + 8) * 64 + nt * 8 + 2 * t] = make_float2(c[nt][2], c[nt][3]);
        }
    } else {
        // ---------------- y^T @ y + colsums ----------------
        const int m0 = (w & 3) * 16;
        const int n0 = (w >> 2) * 32;

        float c[4][4];
#pragma unroll
        for (int n = 0; n < 4; n++)
#pragma unroll
            for (int q = 0; q < 4; q++) c[n][q] = 0.f;

#pragma unroll
        for (int b2 = 0; b2 < 2; b2++) {
            const int ir = band * 2 + b2;
            const uint32_t rowoff = (uint32_t)(ir * 112);
            const uint32_t baA = (uint32_t)((m0 + g) * YROW >> 1) + rowoff;
            const uint32_t baB = (uint32_t)((m0 + g + 8) * YROW >> 1) + rowoff;
#pragma unroll 2
            for (int ks = 0; ks < 14; ks++) {
                uint32_t a0 = yh32[baA + ks * 8 + t];
                uint32_t a2 = yh32[baA + ks * 8 + t + 4];
                uint32_t a1 = yh32[baB + ks * 8 + t];
                uint32_t a3 = yh32[baB + ks * 8 + t + 4];
#pragma unroll
                for (int nt = 0; nt < 4; nt++) {
                    const int n = n0 + nt * 8 + g;
                    uint32_t bb = (uint32_t)(n * YROW >> 1) + rowoff;
                    uint32_t b0 = yh32[bb + ks * 8 + t];
                    uint32_t b1 = yh32[bb + ks * 8 + t + 4];
                    MMA16816(c[nt], a0, a1, a2, a3, b0, b1);
                }
            }
        }

        float* dst = g_ytypart + (size_t)band * 4096;
#pragma unroll
        for (int nt = 0; nt < 4; nt++) {
            const int col = n0 + nt * 8 + 2 * t;
            *(float2*)&dst[(m0 + g) * 64 + col]     = make_float2(c[nt][0], c[nt][1]);
            *(float2*)&dst[(m0 + g + 8) * 64 + col] = make_float2(c[nt][2], c[nt][3]);
        }

        {
            const int oc = tid >> 2, q = tid & 3;
            float s = 0.f;
#pragma unroll
            for (int b2 = 0; b2 < 2; b2++) {
                const uint32_t base = (uint32_t)(oc * YROW >> 1) +
                                      (uint32_t)((band * 2 + b2) * 112) + q * 28;
#pragma unroll 7
                for (int k = 0; k < 28; k++) {
                    uint32_t v = yh32[base + k];
                    __nv_bfloat162 hh = *(__nv_bfloat162*)&v;
                    float2 f = __bfloat1622float2(hh);
                    s += f.x + f.y;
                }
            }
            s += __shfl_xor_sync(0xFFFFFFFFu, s, 1);
            s += __shfl_xor_sync(0xFFFFFFFFu, s, 2);
            if (q == 0) g_colpart[band * OCH + oc] = s;
        }
    }
}

// ======================================================================
// K3: reduce partials + exp_new/gfp. grid 37 x 256.
// ======================================================================
__global__ void k_reduce(const float* __restrict__ exp_avg,
                         float* __restrict__ dout)
{
    int e = blockIdx.x * 256 + threadIdx.x;
    if (e < 8192) {
        const float4* P = (const float4*)g_Cpart;
        float4 s = make_float4(0.f, 0.f, 0.f, 0.f);
#pragma unroll 2
        for (int b = 0; b < MB; b++) {
            float4 v = P[(size_t)b * 8192 + e];
            s.x += v.x; s.y += v.y; s.z += v.z; s.w += v.w;
        }
        ((float4*)g_Cfin)[e] = s;
    } else if (e < 9216) {
        int i = e - 8192;
        const float4* P = (const float4*)g_ytypart;
        float4 s = make_float4(0.f, 0.f, 0.f, 0.f);
#pragma unroll 2
        for (int b = 0; b < MB; b++) {
            float4 v = P[(size_t)b * 1024 + i];
            s.x += v.x; s.y += v.y; s.z += v.z; s.w += v.w;
        }
        ((float4*)g_ytyF)[i] = s;
    }

    if (blockIdx.x == 36) {
        __shared__ float sh[OCH];
        int t = threadIdx.x;
        if (t < OCH) {
            float cs = 0.f;
#pragma unroll 10
            for (int b = 0; b < MB; b++) cs += g_colpart[b * OCH + t];
            float en = 0.99f * exp_avg[t] + (1.0f - 0.99f) * (cs / (float)NB);
            sh[t] = en;
            dout[OUT_OFF_EXP + t] = en;
        }
        __syncthreads();
        if (t < OCH) {
            float s = 0.f;
            for (int i = 0; i < OCH; i++) s += sh[i];
            float A = sh[t] / (s * (1.0f / (float)OCH));
            g_gfp[t] = 0.01f * tanhf(-0.01f * (A - 1.0f)) + 1.0f;
        }
    }
}

// ======================================================================
// K4: weight update.
// ======================================================================
__global__ void k_wupd(const float* __restrict__ W, float* __restrict__ dout)
{
    int idx = blockIdx.x * 256 + threadIdx.x;
    if (idx >= OCH * KTOT) return;
    int oc = idx / KTOT;
    int k = idx - oc * KTOT;
    float dot = 0.f;
#pragma unroll 8
    for (int b = 0; b < OCH; b++)
        dot += g_ytyF[oc * OCH + b] * W[b * KTOT + k];
    const float LRN = (float)(0.005 / 48400.0);
    float d = LRN * (g_Cfin[k * 64 + oc] - dot);
    float wn = fmaxf(W[idx] + d, 0.f);
    dout[OUT_OFF_W + idx] = wn * g_gfp[oc];
}

// ======================================================================
extern "C" void kernel_launch(void* const* d_in, const int* in_sizes, int n_in,
                              void* d_out, int out_size)
{
    const float* x  = (const float*)d_in[0];
    const float* W  = (const float*)d_in[1];
    const float* ea = (const float*)d_in[2];
    float* dout = (float*)d_out;

    const int hebb_smem = 2 * BSZ1 * 4;   // 59392 B
    cudaFuncSetAttribute(k_hebb_mma,
                         cudaFuncAttributeMaxDynamicSharedMemorySize, hebb_smem);

    k_cvt_x<<<(XSZ + 255) / 256, 256>>>(x);
    k_cvt_w<<<(OCH * KTOT + OCH * 440 + 255) / 256, 256>>>(W);
    dim3 g1(2, 220);
    k_conv_mma<<<g1, 224>>>(dout);
    dim3 g2(MB, 5);
    k_hebb_mma<<<g2, 256, hebb_smem>>>();
    k_reduce<<<37, 256>>>(ea, dout);
    k_wupd<<<100, 256>>>(W, dout);
}

// round 12
// speedup vs baseline: 1.4735x; 1.1223x over previous
#include <cuda_runtime.h>
#include <cuda_bf16.h>
#include <cstdint>

// ---------------- problem constants ----------------
#define INS   224
#define NH    220
#define NB    48400
#define ICH   16
#define OCH   64
#define KTOT  400
#define XSZ   (ICH*INS*INS)      // 802816

#define OUT_OFF_W   (OCH*NB)
#define OUT_OFF_EXP (OUT_OFF_W + OCH*KTOT)

#define MB4   55                 // hebb bands (4 image rows each)
#define YROW  49280              // g_yh per-oc size: 220 rows x 224 (pad 4 = 0)

// ---------------- scratch ----------------
__device__ __nv_bfloat16 g_xh[XSZ];
__device__ __nv_bfloat16 g_xl[XSZ];
__device__ __nv_bfloat16 g_xhs[XSZ];         // bf16(x[e+1])
__device__ __nv_bfloat16 g_xls[XSZ];         // lo(x[e+1])
__device__ uint32_t g_xq_h[XSZ];             // pack(hi x[e], hi x[e+220])
__device__ uint32_t g_xq_l[XSZ];
__device__ uint32_t g_xr_h[XSZ];             // pack(hi x[e], hi x[e+49276])
__device__ uint32_t g_xr_l[XSZ];
__device__ __nv_bfloat16 g_Wh[OCH * KTOT];
__device__ __nv_bfloat16 g_Wl[OCH * KTOT];
__device__ __nv_bfloat16 g_yh[OCH * YROW];
__device__ float g_Cpart[MB4 * 512 * OCH];   // 7.2MB
__device__ float g_ytypart[MB4 * OCH * OCH];
__device__ float g_colpart[MB4 * OCH];
__device__ float g_Cfin[512 * OCH];
__device__ float g_ytyF[OCH * OCH];
__device__ float g_gfp[OCH];

#define MMA16816(c, a0,a1,a2,a3, b0,b1) \
  asm volatile("mma.sync.aligned.m16n8k16.row.col.f32.bf16.bf16.f32 " \
    "{%0,%1,%2,%3},{%4,%5,%6,%7},{%8,%9},{%0,%1,%2,%3};" \
    : "+f"((c)[0]),"+f"((c)[1]),"+f"((c)[2]),"+f"((c)[3]) \
    : "r"(a0),"r"(a1),"r"(a2),"r"(a3),"r"(b0),"r"(b1))

#define LDSM4(r0,r1,r2,r3, saddr) \
  asm volatile("ldmatrix.sync.aligned.m8n8.x4.shared.b16 {%0,%1,%2,%3}, [%4];" \
    : "=r"(r0),"=r"(r1),"=r"(r2),"=r"(r3) : "r"(saddr))

__device__ __forceinline__ uint32_t smem_u32(const void* p) {
    return (uint32_t)__cvta_generic_to_shared(p);
}
__device__ __forceinline__ uint32_t pack_bf2(__nv_bfloat16 lo, __nv_bfloat16 hi) {
    unsigned short a = *(unsigned short*)&lo, b = *(unsigned short*)&hi;
    return (uint32_t)a | ((uint32_t)b << 16);
}

// ======================================================================
// K0a: x -> all bf16 pair arrays
// ======================================================================
__global__ void k_cvt_x(const float* __restrict__ x)
{
    int e = blockIdx.x * 256 + threadIdx.x;
    if (e >= XSZ) return;
    float v = x[e];
    __nv_bfloat16 h = __float2bfloat16(v);
    __nv_bfloat16 l = __float2bfloat16(v - __bfloat162float(h));
    g_xh[e] = h; g_xl[e] = l;

    float v1 = (e + 1 < XSZ) ? x[e + 1] : 0.f;
    __nv_bfloat16 h1 = __float2bfloat16(v1);
    g_xhs[e] = h1;
    g_xls[e] = __float2bfloat16(v1 - __bfloat162float(h1));

    float vq = (e + 220 < XSZ) ? x[e + 220] : 0.f;
    __nv_bfloat16 hq = __float2bfloat16(vq);
    __nv_bfloat16 lq = __float2bfloat16(vq - __bfloat162float(hq));
    g_xq_h[e] = pack_bf2(h, hq);
    g_xq_l[e] = pack_bf2(l, lq);

    float vr = (e + 49276 < XSZ) ? x[e + 49276] : 0.f;
    __nv_bfloat16 hr = __float2bfloat16(vr);
    __nv_bfloat16 lr = __float2bfloat16(vr - __bfloat162float(hr));
    g_xr_h[e] = pack_bf2(h, hr);
    g_xr_l[e] = pack_bf2(l, lr);
}

// ======================================================================
// K0b: W -> bf16 hi/lo ; zero g_yh row pads
// ======================================================================
__global__ void k_cvt_w(const float* __restrict__ W)
{
    int idx = blockIdx.x * 256 + threadIdx.x;
    if (idx < OCH * KTOT) {
        float v = W[idx];
        __nv_bfloat16 h = __float2bfloat16(v);
        g_Wh[idx] = h;
        g_Wl[idx] = __float2bfloat16(v - __bfloat162float(h));
    } else if (idx < OCH * KTOT + OCH * 220 * 2) {
        int p = idx - OCH * KTOT;
        int oc = p / 440, rem = p - oc * 440;
        int r = rem >> 1, half = rem & 1;
        uint32_t* yh32 = (uint32_t*)g_yh;
        yh32[((oc * YROW + r * 224 + 220) >> 1) + half] = 0u;
    }
}

// ======================================================================
// A pair-load for conv: element pair (kb, kb+1) at pixel column eb(+8).
// ======================================================================
__device__ __forceinline__ void loadpairs(int kb, int eb, int pxA,
    uint32_t& h0, uint32_t& h1, uint32_t& l0, uint32_t& l1)
{
    int q = kb / 5;
    int kj = kb - q * 5;
    int ic = q / 5;
    int e = q * 224 + ic * 49056 + eb + kj;
    if (kj == 4) {
        bool icx = (q - ic * 5) == 4;
        const uint32_t* ph = icx ? g_xr_h : g_xq_h;
        const uint32_t* pl = icx ? g_xr_l : g_xq_l;
        h0 = ph[e]; h1 = ph[e + 8];
        l0 = pl[e]; l1 = pl[e + 8];
    } else {
        int par = (pxA + kj) & 1;
        const uint32_t* ph = par ? (const uint32_t*)g_xhs : (const uint32_t*)g_xh;
        const uint32_t* pl = par ? (const uint32_t*)g_xls : (const uint32_t*)g_xl;
        int w0 = e >> 1;
        h0 = ph[w0]; h1 = ph[w0 + 4];
        l0 = pl[w0]; l1 = pl[w0 + 4];
    }
}

// ======================================================================
// K1: conv + inhibition, split-bf16 MMA, A direct-global, W via LDSM.
// grid (2, 220), 224 thr (7 warps). Warp = 16 px x 64 oc.  (R9 verbatim)
// ======================================================================
#define WPITCH 20

__global__ void __launch_bounds__(224, 4)
k_conv_mma(float* __restrict__ dout)
{
    __shared__ uint32_t wsh[64 * WPITCH];
    __shared__ uint32_t wsl[64 * WPITCH];

    const int tid = threadIdx.x;
    const int w = tid >> 5, lane = tid & 31;
    const int g = lane >> 2, t = lane & 3;
    const int h = blockIdx.x;
    const int i = blockIdx.y;
    const int J0 = h * 108;
    const int pxA = (w << 4) + g;
    const int eb = i * 224 + J0 + pxA;

    const int nrow_off = ((lane >> 4) & 1) * 8 + (lane & 7);
    const int k_off = ((lane >> 3) & 1) * 4;
    const uint32_t wsh_s = smem_u32(wsh);
    const uint32_t wsl_s = smem_u32(wsl);
    const uint32_t* wh2g = (const uint32_t*)g_Wh;
    const uint32_t* wl2g = (const uint32_t*)g_Wl;

    float c[8][4];
#pragma unroll
    for (int nt = 0; nt < 8; nt++)
#pragma unroll
        for (int q = 0; q < 4; q++) c[nt][q] = 0.f;

    for (int s = 0; s < 13; s++) {
        __syncthreads();
        const int k0s = s * 32;
        const int nu = (s < 12) ? 16 : 8;
        for (int idx = tid; idx < 64 * nu; idx += 224) {
            int row = idx / nu, u = idx - row * nu;
            wsh[row * WPITCH + u] = wh2g[row * 200 + (k0s >> 1) + u];
            wsl[row * WPITCH + u] = wl2g[row * 200 + (k0s >> 1) + u];
        }
        __syncthreads();

        const int nks = (s < 12) ? 2 : 1;
        for (int ksl = 0; ksl < nks; ksl++) {
            const int kb0 = k0s + ksl * 16 + 2 * t;
            uint32_t ah0, ah1, al0, al1, ah2, ah3, al2, al3;
            loadpairs(kb0,     eb, pxA, ah0, ah1, al0, al1);
            loadpairs(kb0 + 8, eb, pxA, ah2, ah3, al2, al3);

            const uint32_t wbase = ((uint32_t)(nrow_off * WPITCH + ksl * 8 + k_off)) * 4;
#pragma unroll
            for (int p = 0; p < 4; p++) {
                uint32_t bh0, bh1, bh2, bh3, bl0, bl1, bl2, bl3;
                const uint32_t off = wbase + (uint32_t)(p * 16 * WPITCH) * 4;
                LDSM4(bh0, bh1, bh2, bh3, wsh_s + off);
                LDSM4(bl0, bl1, bl2, bl3, wsl_s + off);
                MMA16816(c[2 * p],     ah0, ah1, ah2, ah3, bh0, bh1);
                MMA16816(c[2 * p],     al0, al1, al2, al3, bh0, bh1);
                MMA16816(c[2 * p],     ah0, ah1, ah2, ah3, bl0, bl1);
                MMA16816(c[2 * p + 1], ah0, ah1, ah2, ah3, bh2, bh3);
                MMA16816(c[2 * p + 1], al0, al1, al2, al3, bh2, bh3);
                MMA16816(c[2 * p + 1], ah0, ah1, ah2, ah3, bl2, bl3);
            }
        }
    }

    // ---- inhibition + writeback ----
    float m0 = 0.f, m1 = 0.f;
#pragma unroll
    for (int nt = 0; nt < 8; nt++) {
        m0 = fmaxf(m0, fmaxf(c[nt][0], c[nt][1]));
        m1 = fmaxf(m1, fmaxf(c[nt][2], c[nt][3]));
    }
    m0 = fmaxf(m0, __shfl_xor_sync(0xFFFFFFFFu, m0, 1));
    m0 = fmaxf(m0, __shfl_xor_sync(0xFFFFFFFFu, m0, 2));
    m1 = fmaxf(m1, __shfl_xor_sync(0xFFFFFFFFu, m1, 1));
    m1 = fmaxf(m1, __shfl_xor_sync(0xFFFFFFFFu, m1, 2));
    const float inv0 = 1.f / (m0 + 1e-9f);
    const float inv1 = 1.f / (m1 + 1e-9f);

    const int pxg = i * NH + J0 + pxA;
    const int pyg = i * 224 + J0 + pxA;
#pragma unroll
    for (int nt = 0; nt < 8; nt++) {
        const int oc = nt * 8 + 2 * t;
        float v;
        v = fmaxf(c[nt][0], 0.f) * inv0; v = (v * v) * (v * v) * v;
        dout[(size_t)oc * NB + pxg] = v;
        g_yh[(size_t)oc * YROW + pyg] = __float2bfloat16(v);
        v = fmaxf(c[nt][1], 0.f) * inv0; v = (v * v) * (v * v) * v;
        dout[(size_t)(oc + 1) * NB + pxg] = v;
        g_yh[(size_t)(oc + 1) * YROW + pyg] = __float2bfloat16(v);
        v = fmaxf(c[nt][2], 0.f) * inv1; v = (v * v) * (v * v) * v;
        dout[(size_t)oc * NB + pxg + 8] = v;
        g_yh[(size_t)oc * YROW + pyg + 8] = __float2bfloat16(v);
        v = fmaxf(c[nt][3], 0.f) * inv1; v = (v * v) * (v * v) * v;
        dout[(size_t)(oc + 1) * NB + pxg + 8] = v;
        g_yh[(size_t)(oc + 1) * YROW + pyg + 8] = __float2bfloat16(v);
    }
}

// ======================================================================
// K2: fused Hebbian GEMMs. grid (55, 5), 256 thr, 29KB dyn smem.
//   kt 0..3 : y^T @ xf over 4 rows (A direct-global, B smem+LDSM)
//   kt == 4 : y^T @ y + colsums over 4 rows (frag-direct global)
// ======================================================================
#define BPITCH 116
#define BSZ    (64 * BPITCH)       // 7424 u32: 29696 B

extern __shared__ uint32_t s_B[];

__global__ void __launch_bounds__(256, 4)
k_hebb_mma()
{
    const int tid  = threadIdx.x;
    const int band = blockIdx.x;     // 0..54, rows 4*band .. 4*band+3
    const int kt   = blockIdx.y;
    const int w    = tid >> 5;
    const int lane = tid & 31;
    const int g    = lane >> 2;
    const int t    = lane & 3;

    const uint32_t* yh32 = (const uint32_t*)g_yh;

    if (kt < 4) {
        // ---------------- y^T @ xf ----------------
        const uint32_t* xh32  = (const uint32_t*)g_xh;
        const uint32_t* xhs32 = (const uint32_t*)g_xhs;

        int rA = kt * 128 + w * 16 + g;
        int rB = rA + 8;
        int rc0 = 0, rc1 = 0;
        const uint32_t *p0 = xh32, *p1 = xh32;
        if (rA < KTOT) {
            int ic = rA / 25, rem = rA - ic * 25;
            int ki = rem / 5, kj = rem - ki * 5;
            rc0 = ic * 50176 + ki * 224 + kj;
            if (kj & 1) p0 = xhs32;
        }
        if (rB < KTOT) {
            int ic = rB / 25, rem = rB - ic * 25;
            int ki = rem / 5, kj = rem - ki * 5;
            rc1 = ic * 50176 + ki * 224 + kj;
            if (kj & 1) p1 = xhs32;
        }

        const uint32_t bsm = smem_u32(s_B);
        const int nrow_off = ((lane >> 4) & 1) * 8 + (lane & 7);
        const int k_off = ((lane >> 3) & 1) * 4;

        float c[8][4];
#pragma unroll
        for (int n = 0; n < 8; n++)
#pragma unroll
            for (int q = 0; q < 4; q++) c[n][q] = 0.f;

#pragma unroll
        for (int b2 = 0; b2 < 4; b2++) {
            const int ir = band * 4 + b2;
            __syncthreads();
            // fill B for this band row
            for (int idx = tid; idx < 64 * 128; idx += 256) {
                int row = idx >> 7, pc = idx & 127;
                if (pc < 112) {
                    uint32_t v = 0;
                    if (pc < 110)
                        v = yh32[((row * YROW + ir * 224) >> 1) + pc];
                    s_B[row * BPITCH + pc] = v;
                }
            }
            __syncthreads();

            const uint32_t ba0 = (uint32_t)(rc0 + ir * 224) >> 1;
            const uint32_t ba1 = (uint32_t)(rc1 + ir * 224) >> 1;
#pragma unroll
            for (int ks = 0; ks < 14; ks++) {
                uint32_t a0 = p0[ba0 + ks * 8 + t];
                uint32_t a2 = p0[ba0 + ks * 8 + t + 4];
                uint32_t a1 = p1[ba1 + ks * 8 + t];
                uint32_t a3 = p1[ba1 + ks * 8 + t + 4];
#pragma unroll
                for (int p = 0; p < 4; p++) {
                    uint32_t b0, b1, b2r, b3;
                    uint32_t addr = bsm + (uint32_t)((p * 16 + nrow_off) * BPITCH +
                                                     ks * 8 + k_off) * 4;
                    LDSM4(b0, b1, b2r, b3, addr);
                    MMA16816(c[2 * p],     a0, a1, a2, a3, b0, b1);
                    MMA16816(c[2 * p + 1], a0, a1, a2, a3, b2r, b3);
                }
            }
        }

        float* dst = g_Cpart + ((size_t)band * 512 + kt * 128 + w * 16) * 64;
#pragma unroll
        for (int nt = 0; nt < 8; nt++) {
            *(float2*)&dst[(g)     * 64 + nt * 8 + 2 * t] = make_float2(c[nt][0], c[nt][1]);
            *(float2*)&dst[(g + 8) * 64 + nt * 8 + 2 * t] = make_float2(c[nt][2], c[nt][3]);
        }
    } else {
        // ---------------- y^T @ y + colsums ----------------
        const int m0 = (w & 3) * 16;
        const int n0 = (w >> 2) * 32;

        float c[4][4];
#pragma unroll
        for (int n = 0; n < 4; n++)
#pragma unroll
            for (int q = 0; q < 4; q++) c[n][q] = 0.f;

#pragma unroll
        for (int b2 = 0; b2 < 4; b2++) {
            const int ir = band * 4 + b2;
            const uint32_t rowoff = (uint32_t)(ir * 112);
            const uint32_t baA = (uint32_t)((m0 + g) * YROW >> 1) + rowoff;
            const uint32_t baB = (uint32_t)((m0 + g + 8) * YROW >> 1) + rowoff;
#pragma unroll 2
            for (int ks = 0; ks < 14; ks++) {
                uint32_t a0 = yh32[baA + ks * 8 + t];
                uint32_t a2 = yh32[baA + ks * 8 + t + 4];
                uint32_t a1 = yh32[baB + ks * 8 + t];
                uint32_t a3 = yh32[baB + ks * 8 + t + 4];
#pragma unroll
                for (int nt = 0; nt < 4; nt++) {
                    const int n = n0 + nt * 8 + g;
                    uint32_t bb = (uint32_t)(n * YROW >> 1) + rowoff;
                    uint32_t b0 = yh32[bb + ks * 8 + t];
                    uint32_t b1 = yh32[bb + ks * 8 + t + 4];
                    MMA16816(c[nt], a0, a1, a2, a3, b0, b1);
                }
            }
        }

        float* dst = g_ytypart + (size_t)band * 4096;
#pragma unroll
        for (int nt = 0; nt < 4; nt++) {
            const int col = n0 + nt * 8 + 2 * t;
            *(float2*)&dst[(m0 + g) * 64 + col]     = make_float2(c[nt][0], c[nt][1]);
            *(float2*)&dst[(m0 + g + 8) * 64 + col] = make_float2(c[nt][2], c[nt][3]);
        }

        // colsums over 4 rows of band
        {
            const int oc = tid >> 2, q = tid & 3;
            float s = 0.f;
#pragma unroll
            for (int b2 = 0; b2 < 4; b2++) {
                const uint32_t base = (uint32_t)(oc * YROW >> 1) +
                                      (uint32_t)((band * 4 + b2) * 112) + q * 28;
#pragma unroll 7
                for (int k = 0; k < 28; k++) {
                    uint32_t v = yh32[base + k];
                    __nv_bfloat162 hh = *(__nv_bfloat162*)&v;
                    float2 f = __bfloat1622float2(hh);
                    s += f.x + f.y;
                }
            }
            s += __shfl_xor_sync(0xFFFFFFFFu, s, 1);
            s += __shfl_xor_sync(0xFFFFFFFFu, s, 2);
            if (q == 0) g_colpart[band * OCH + oc] = s;
        }
    }
}

// ======================================================================
// K3: reduce partials + exp_new/gfp. grid 37 x 256.
// ======================================================================
__global__ void k_reduce(const float* __restrict__ exp_avg,
                         float* __restrict__ dout)
{
    int e = blockIdx.x * 256 + threadIdx.x;
    if (e < 8192) {
        const float4* P = (const float4*)g_Cpart;
        float4 s = make_float4(0.f, 0.f, 0.f, 0.f);
#pragma unroll 5
        for (int b = 0; b < MB4; b++) {
            float4 v = P[(size_t)b * 8192 + e];
            s.x += v.x; s.y += v.y; s.z += v.z; s.w += v.w;
        }
        ((float4*)g_Cfin)[e] = s;
    } else if (e < 9216) {
        int i = e - 8192;
        const float4* P = (const float4*)g_ytypart;
        float4 s = make_float4(0.f, 0.f, 0.f, 0.f);
#pragma unroll 5
        for (int b = 0; b < MB4; b++) {
            float4 v = P[(size_t)b * 1024 + i];
            s.x += v.x; s.y += v.y; s.z += v.z; s.w += v.w;
        }
        ((float4*)g_ytyF)[i] = s;
    }

    if (blockIdx.x == 36) {
        __shared__ float sh[OCH];
        int t = threadIdx.x;
        if (t < OCH) {
            float cs = 0.f;
#pragma unroll 5
            for (int b = 0; b < MB4; b++) cs += g_colpart[b * OCH + t];
            float en = 0.99f * exp_avg[t] + (1.0f - 0.99f) * (cs / (float)NB);
            sh[t] = en;
            dout[OUT_OFF_EXP + t] = en;
        }
        __syncthreads();
        if (t < OCH) {
            float s = 0.f;
            for (int i = 0; i < OCH; i++) s += sh[i];
            float A = sh[t] / (s * (1.0f / (float)OCH));
            g_gfp[t] = 0.01f * tanhf(-0.01f * (A - 1.0f)) + 1.0f;
        }
    }
}

// ======================================================================
// K4: weight update.
// ======================================================================
__global__ void k_wupd(const float* __restrict__ W, float* __restrict__ dout)
{
    int idx = blockIdx.x * 256 + threadIdx.x;
    if (idx >= OCH * KTOT) return;
    int oc = idx / KTOT;
    int k = idx - oc * KTOT;
    float dot = 0.f;
#pragma unroll 8
    for (int b = 0; b < OCH; b++)
        dot += g_ytyF[oc * OCH + b] * W[b * KTOT + k];
    const float LRN = (float)(0.005 / 48400.0);
    float d = LRN * (g_Cfin[k * 64 + oc] - dot);
    float wn = fmaxf(W[idx] + d, 0.f);
    dout[OUT_OFF_W + idx] = wn * g_gfp[oc];
}

// ======================================================================
extern "C" void kernel_launch(void* const* d_in, const int* in_sizes, int n_in,
                              void* d_out, int out_size)
{
    const float* x  = (const float*)d_in[0];
    const float* W  = (const float*)d_in[1];
    const float* ea = (const float*)d_in[2];
    float* dout = (float*)d_out;

    const int hebb_smem = BSZ * 4;   // 29696 B

    k_cvt_x<<<(XSZ + 255) / 256, 256>>>(x);
    k_cvt_w<<<(OCH * KTOT + OCH * 440 + 255) / 256, 256>>>(W);
    dim3 g1(2, 220);
    k_conv_mma<<<g1, 224>>>(dout);
    dim3 g2(MB4, 5);
    k_hebb_mma<<<g2, 256, hebb_smem>>>();
    k_reduce<<<37, 256>>>(ea, dout);
    k_wupd<<<100, 256>>>(W, dout);
}

// round 13
// speedup vs baseline: 1.7085x; 1.1595x over previous
#include <cuda_runtime.h>
#include <cuda_bf16.h>
#include <cstdint>

// ---------------- problem constants ----------------
#define INS   224
#define NH    220
#define NB    48400
#define ICH   16
#define OCH   64
#define KTOT  400
#define XSZ   (ICH*INS*INS)      // 802816

#define OUT_OFF_W   (OCH*NB)
#define OUT_OFF_EXP (OUT_OFF_W + OCH*KTOT)

#define MB4   55                 // hebb bands (4 image rows each)
#define YROW  49280              // g_yh per-oc size: 220 rows x 224 (pad 4 = 0)

// ---------------- scratch ----------------
__device__ __nv_bfloat16 g_xh[XSZ];
__device__ __nv_bfloat16 g_xl[XSZ];
__device__ __nv_bfloat16 g_xhs[XSZ];         // bf16(x[e+1])
__device__ __nv_bfloat16 g_xls[XSZ];         // lo(x[e+1])
__device__ uint32_t g_xq_h[XSZ];             // pack(hi x[e], hi x[e+220])
__device__ uint32_t g_xq_l[XSZ];
__device__ uint32_t g_xr_h[XSZ];             // pack(hi x[e], hi x[e+49276])
__device__ uint32_t g_xr_l[XSZ];
__device__ __nv_bfloat16 g_Wh[OCH * KTOT];
__device__ __nv_bfloat16 g_Wl[OCH * KTOT];
__device__ __nv_bfloat16 g_yh[OCH * YROW];
__device__ float g_Cpart[MB4 * 512 * OCH];   // 7.2MB
__device__ float g_ytypart[MB4 * OCH * OCH];
__device__ float g_colpart[MB4 * OCH];
__device__ float g_Cfin[512 * OCH];
__device__ float g_ytyF[OCH * OCH];
__device__ float g_gfp[OCH];

#define MMA16816(c, a0,a1,a2,a3, b0,b1) \
  asm volatile("mma.sync.aligned.m16n8k16.row.col.f32.bf16.bf16.f32 " \
    "{%0,%1,%2,%3},{%4,%5,%6,%7},{%8,%9},{%0,%1,%2,%3};" \
    : "+f"((c)[0]),"+f"((c)[1]),"+f"((c)[2]),"+f"((c)[3]) \
    : "r"(a0),"r"(a1),"r"(a2),"r"(a3),"r"(b0),"r"(b1))

#define LDSM4(r0,r1,r2,r3, saddr) \
  asm volatile("ldmatrix.sync.aligned.m8n8.x4.shared.b16 {%0,%1,%2,%3}, [%4];" \
    : "=r"(r0),"=r"(r1),"=r"(r2),"=r"(r3) : "r"(saddr))

#define CP_ASYNC4(saddr, gptr) \
  asm volatile("cp.async.ca.shared.global [%0], [%1], 4;" \
    :: "r"(saddr), "l"(gptr) : "memory")
#define CP_COMMIT()   asm volatile("cp.async.commit_group;" ::: "memory")
#define CP_WAIT_ALL() asm volatile("cp.async.wait_group 0;" ::: "memory")

__device__ __forceinline__ uint32_t smem_u32(const void* p) {
    return (uint32_t)__cvta_generic_to_shared(p);
}
__device__ __forceinline__ uint32_t pack_bf2(__nv_bfloat16 lo, __nv_bfloat16 hi) {
    unsigned short a = *(unsigned short*)&lo, b = *(unsigned short*)&hi;
    return (uint32_t)a | ((uint32_t)b << 16);
}

// ======================================================================
// K0a: x -> all bf16 pair arrays
// ======================================================================
__global__ void k_cvt_x(const float* __restrict__ x)
{
    int e = blockIdx.x * 256 + threadIdx.x;
    if (e >= XSZ) return;
    float v = x[e];
    __nv_bfloat16 h = __float2bfloat16(v);
    __nv_bfloat16 l = __float2bfloat16(v - __bfloat162float(h));
    g_xh[e] = h; g_xl[e] = l;

    float v1 = (e + 1 < XSZ) ? x[e + 1] : 0.f;
    __nv_bfloat16 h1 = __float2bfloat16(v1);
    g_xhs[e] = h1;
    g_xls[e] = __float2bfloat16(v1 - __bfloat162float(h1));

    float vq = (e + 220 < XSZ) ? x[e + 220] : 0.f;
    __nv_bfloat16 hq = __float2bfloat16(vq);
    __nv_bfloat16 lq = __float2bfloat16(vq - __bfloat162float(hq));
    g_xq_h[e] = pack_bf2(h, hq);
    g_xq_l[e] = pack_bf2(l, lq);

    float vr = (e + 49276 < XSZ) ? x[e + 49276] : 0.f;
    __nv_bfloat16 hr = __float2bfloat16(vr);
    __nv_bfloat16 lr = __float2bfloat16(vr - __bfloat162float(hr));
    g_xr_h[e] = pack_bf2(h, hr);
    g_xr_l[e] = pack_bf2(l, lr);
}

// ======================================================================
// K0b: W -> bf16 hi/lo ; zero g_yh row pads
// ======================================================================
__global__ void k_cvt_w(const float* __restrict__ W)
{
    int idx = blockIdx.x * 256 + threadIdx.x;
    if (idx < OCH * KTOT) {
        float v = W[idx];
        __nv_bfloat16 h = __float2bfloat16(v);
        g_Wh[idx] = h;
        g_Wl[idx] = __float2bfloat16(v - __bfloat162float(h));
    } else if (idx < OCH * KTOT + OCH * 220 * 2) {
        int p = idx - OCH * KTOT;
        int oc = p / 440, rem = p - oc * 440;
        int r = rem >> 1, half = rem & 1;
        uint32_t* yh32 = (uint32_t*)g_yh;
        yh32[((oc * YROW + r * 224 + 220) >> 1) + half] = 0u;
    }
}

// ======================================================================
// A pair-load for conv: element pair (kb, kb+1) at pixel column eb(+8).
// ======================================================================
__device__ __forceinline__ void loadpairs(int kb, int eb, int pxA,
    uint32_t& h0, uint32_t& h1, uint32_t& l0, uint32_t& l1)
{
    int q = kb / 5;
    int kj = kb - q * 5;
    int ic = q / 5;
    int e = q * 224 + ic * 49056 + eb + kj;
    if (kj == 4) {
        bool icx = (q - ic * 5) == 4;
        const uint32_t* ph = icx ? g_xr_h : g_xq_h;
        const uint32_t* pl = icx ? g_xr_l : g_xq_l;
        h0 = ph[e]; h1 = ph[e + 8];
        l0 = pl[e]; l1 = pl[e + 8];
    } else {
        int par = (pxA + kj) & 1;
        const uint32_t* ph = par ? (const uint32_t*)g_xhs : (const uint32_t*)g_xh;
        const uint32_t* pl = par ? (const uint32_t*)g_xls : (const uint32_t*)g_xl;
        int w0 = e >> 1;
        h0 = ph[w0]; h1 = ph[w0 + 4];
        l0 = pl[w0]; l1 = pl[w0 + 4];
    }
}

// ======================================================================
// K1: conv + inhibition, split-bf16 MMA, A direct-global, W via LDSM,
// W-chunks double-buffered with cp.async.
// grid (2, 220), 224 thr (7 warps). Warp = 16 px x 64 oc.
// ======================================================================
#define WPITCH 20
#define WBUF   (64 * WPITCH)

__global__ void __launch_bounds__(224, 4)
k_conv_mma(float* __restrict__ dout)
{
    __shared__ uint32_t wsh[2 * WBUF];
    __shared__ uint32_t wsl[2 * WBUF];

    const int tid = threadIdx.x;
    const int w = tid >> 5, lane = tid & 31;
    const int g = lane >> 2, t = lane & 3;
    const int h = blockIdx.x;
    const int i = blockIdx.y;
    const int J0 = h * 108;
    const int pxA = (w << 4) + g;
    const int eb = i * 224 + J0 + pxA;

    const int nrow_off = ((lane >> 4) & 1) * 8 + (lane & 7);
    const int k_off = ((lane >> 3) & 1) * 4;
    const uint32_t wsh_s = smem_u32(wsh);
    const uint32_t wsl_s = smem_u32(wsl);
    const uint32_t* wh2g = (const uint32_t*)g_Wh;
    const uint32_t* wl2g = (const uint32_t*)g_Wl;

    float c[8][4];
#pragma unroll
    for (int nt = 0; nt < 8; nt++)
#pragma unroll
        for (int q = 0; q < 4; q++) c[nt][q] = 0.f;

    // ---- async fill of W chunk s into buffer buf ----
    auto fillW = [&](int s, int buf) {
        const int nu = (s < 12) ? 16 : 8;
        const int base = s * 16;
        for (int idx = tid; idx < 64 * nu; idx += 224) {
            int row, u;
            if (nu == 16) { row = idx >> 4; u = idx & 15; }
            else          { row = idx >> 3; u = idx & 7;  }
            uint32_t so = (uint32_t)(buf * WBUF + row * WPITCH + u) * 4;
            CP_ASYNC4(wsh_s + so, wh2g + row * 200 + base + u);
            CP_ASYNC4(wsl_s + so, wl2g + row * 200 + base + u);
        }
    };

    fillW(0, 0);
    CP_COMMIT();

    for (int s = 0; s < 13; s++) {
        CP_WAIT_ALL();
        __syncthreads();
        if (s < 12) { fillW(s + 1, (s + 1) & 1); CP_COMMIT(); }

        const int k0s = s * 32;
        const int nks = (s < 12) ? 2 : 1;
        const uint32_t bufoff = (uint32_t)((s & 1) * WBUF) * 4;

        for (int ksl = 0; ksl < nks; ksl++) {
            const int kb0 = k0s + ksl * 16 + 2 * t;
            uint32_t ah0, ah1, al0, al1, ah2, ah3, al2, al3;
            loadpairs(kb0,     eb, pxA, ah0, ah1, al0, al1);
            loadpairs(kb0 + 8, eb, pxA, ah2, ah3, al2, al3);

            const uint32_t wbase = bufoff +
                ((uint32_t)(nrow_off * WPITCH + ksl * 8 + k_off)) * 4;
#pragma unroll
            for (int p = 0; p < 4; p++) {
                uint32_t bh0, bh1, bh2, bh3, bl0, bl1, bl2, bl3;
                const uint32_t off = wbase + (uint32_t)(p * 16 * WPITCH) * 4;
                LDSM4(bh0, bh1, bh2, bh3, wsh_s + off);
                LDSM4(bl0, bl1, bl2, bl3, wsl_s + off);
                MMA16816(c[2 * p],     ah0, ah1, ah2, ah3, bh0, bh1);
                MMA16816(c[2 * p],     al0, al1, al2, al3, bh0, bh1);
                MMA16816(c[2 * p],     ah0, ah1, ah2, ah3, bl0, bl1);
                MMA16816(c[2 * p + 1], ah0, ah1, ah2, ah3, bh2, bh3);
                MMA16816(c[2 * p + 1], al0, al1, al2, al3, bh2, bh3);
                MMA16816(c[2 * p + 1], ah0, ah1, ah2, ah3, bl2, bl3);
            }
        }
        __syncthreads();   // all reads of this buffer done before its refill (s+2)
    }

    // ---- inhibition + writeback ----
    float m0 = 0.f, m1 = 0.f;
#pragma unroll
    for (int nt = 0; nt < 8; nt++) {
        m0 = fmaxf(m0, fmaxf(c[nt][0], c[nt][1]));
        m1 = fmaxf(m1, fmaxf(c[nt][2], c[nt][3]));
    }
    m0 = fmaxf(m0, __shfl_xor_sync(0xFFFFFFFFu, m0, 1));
    m0 = fmaxf(m0, __shfl_xor_sync(0xFFFFFFFFu, m0, 2));
    m1 = fmaxf(m1, __shfl_xor_sync(0xFFFFFFFFu, m1, 1));
    m1 = fmaxf(m1, __shfl_xor_sync(0xFFFFFFFFu, m1, 2));
    const float inv0 = 1.f / (m0 + 1e-9f);
    const float inv1 = 1.f / (m1 + 1e-9f);

    const int pxg = i * NH + J0 + pxA;
    const int pyg = i * 224 + J0 + pxA;
#pragma unroll
    for (int nt = 0; nt < 8; nt++) {
        const int oc = nt * 8 + 2 * t;
        float v;
        v = fmaxf(c[nt][0], 0.f) * inv0; v = (v * v) * (v * v) * v;
        dout[(size_t)oc * NB + pxg] = v;
        g_yh[(size_t)oc * YROW + pyg] = __float2bfloat16(v);
        v = fmaxf(c[nt][1], 0.f) * inv0; v = (v * v) * (v * v) * v;
        dout[(size_t)(oc + 1) * NB + pxg] = v;
        g_yh[(size_t)(oc + 1) * YROW + pyg] = __float2bfloat16(v);
        v = fmaxf(c[nt][2], 0.f) * inv1; v = (v * v) * (v * v) * v;
        dout[(size_t)oc * NB + pxg + 8] = v;
        g_yh[(size_t)oc * YROW + pyg + 8] = __float2bfloat16(v);
        v = fmaxf(c[nt][3], 0.f) * inv1; v = (v * v) * (v * v) * v;
        dout[(size_t)(oc + 1) * NB + pxg + 8] = v;
        g_yh[(size_t)(oc + 1) * YROW + pyg + 8] = __float2bfloat16(v);
    }
}

// ======================================================================
// K2: fused Hebbian GEMMs. grid (55, 5), 256 thr, 59.4KB dyn smem.
//   kt 0..3 : y^T @ xf over 4 rows (A direct-global,
//             B double-buffered via cp.async + LDSM)
//   kt == 4 : y^T @ y + colsums over 4 rows (frag-direct global)
// ======================================================================
#define BPITCH 116
#define BSZ    (64 * BPITCH)       // 7424 u32 per buffer

extern __shared__ uint32_t s_B[];  // 2 * BSZ

__global__ void __launch_bounds__(256, 4)
k_hebb_mma()
{
    const int tid  = threadIdx.x;
    const int band = blockIdx.x;     // rows 4*band .. 4*band+3
    const int kt   = blockIdx.y;
    const int w    = tid >> 5;
    const int lane = tid & 31;
    const int g    = lane >> 2;
    const int t    = lane & 3;

    const uint32_t* yh32 = (const uint32_t*)g_yh;

    if (kt < 4) {
        // ---------------- y^T @ xf ----------------
        const uint32_t* xh32  = (const uint32_t*)g_xh;
        const uint32_t* xhs32 = (const uint32_t*)g_xhs;

        int rA = kt * 128 + w * 16 + g;
        int rB = rA + 8;
        int rc0 = 0, rc1 = 0;
        const uint32_t *p0 = xh32, *p1 = xh32;
        if (rA < KTOT) {
            int ic = rA / 25, rem = rA - ic * 25;
            int ki = rem / 5, kj = rem - ki * 5;
            rc0 = ic * 50176 + ki * 224 + kj;
            if (kj & 1) p0 = xhs32;
        }
        if (rB < KTOT) {
            int ic = rB / 25, rem = rB - ic * 25;
            int ki = rem / 5, kj = rem - ki * 5;
            rc1 = ic * 50176 + ki * 224 + kj;
            if (kj & 1) p1 = xhs32;
        }

        const uint32_t bsm = smem_u32(s_B);
        const int nrow_off = ((lane >> 4) & 1) * 8 + (lane & 7);
        const int k_off = ((lane >> 3) & 1) * 4;

        // zero the pad words of both buffers (written once, stay zero)
        {
            int buf = tid >> 7, rem = tid & 127;
            int row = rem >> 1, p = rem & 1;
            s_B[buf * BSZ + row * BPITCH + 110 + p] = 0u;
        }

        // async fill of B for image row ir into buffer buf
        auto fillB = [&](int ir, int buf) {
            for (int idx = tid; idx < 64 * 112; idx += 256) {
                int row = idx / 112, pc = idx - row * 112;
                if (pc < 110) {
                    uint32_t so = (uint32_t)(buf * BSZ + row * BPITCH + pc) * 4;
                    CP_ASYNC4(bsm + so, yh32 + ((row * YROW + ir * 224) >> 1) + pc);
                }
            }
        };

        float c[8][4];
#pragma unroll
        for (int n = 0; n < 8; n++)
#pragma unroll
            for (int q = 0; q < 4; q++) c[n][q] = 0.f;

        fillB(band * 4, 0);
        CP_COMMIT();

#pragma unroll
        for (int b2 = 0; b2 < 4; b2++) {
            const int ir = band * 4 + b2;
            CP_WAIT_ALL();
            __syncthreads();
            if (b2 < 3) { fillB(ir + 1, (b2 + 1) & 1); CP_COMMIT(); }

            const uint32_t ba0 = (uint32_t)(rc0 + ir * 224) >> 1;
            const uint32_t ba1 = (uint32_t)(rc1 + ir * 224) >> 1;
            const uint32_t bufoff = (uint32_t)((b2 & 1) * BSZ) * 4;
#pragma unroll
            for (int ks = 0; ks < 14; ks++) {
                uint32_t a0 = p0[ba0 + ks * 8 + t];
                uint32_t a2 = p0[ba0 + ks * 8 + t + 4];
                uint32_t a1 = p1[ba1 + ks * 8 + t];
                uint32_t a3 = p1[ba1 + ks * 8 + t + 4];
#pragma unroll
                for (int p = 0; p < 4; p++) {
                    uint32_t b0, b1, b2r, b3;
                    uint32_t addr = bsm + bufoff +
                        (uint32_t)((p * 16 + nrow_off) * BPITCH + ks * 8 + k_off) * 4;
                    LDSM4(b0, b1, b2r, b3, addr);
                    MMA16816(c[2 * p],     a0, a1, a2, a3, b0, b1);
                    MMA16816(c[2 * p + 1], a0, a1, a2, a3, b2r, b3);
                }
            }
            __syncthreads();   // reads done before this buffer's refill (b2+2)
        }

        float* dst = g_Cpart + ((size_t)band * 512 + kt * 128 + w * 16) * 64;
#pragma unroll
        for (int nt = 0; nt < 8; nt++) {
            *(float2*)&dst[(g)     * 64 + nt * 8 + 2 * t] = make_float2(c[nt][0], c[nt][1]);
            *(float2*)&dst[(g + 8) * 64 + nt * 8 + 2 * t] = make_float2(c[nt][2], c[nt][3]);
        }
    } else {
        // ---------------- y^T @ y + colsums ----------------
        const int m0 = (w & 3) * 16;
        const int n0 = (w >> 2) * 32;

        float c[4][4];
#pragma unroll
        for (int n = 0; n < 4; n++)
#pragma unroll
            for (int q = 0; q < 4; q++) c[n][q] = 0.f;

#pragma unroll
        for (int b2 = 0; b2 < 4; b2++) {
            const int ir = band * 4 + b2;
            const uint32_t rowoff = (uint32_t)(ir * 112);
            const uint32_t baA = (uint32_t)((m0 + g) * YROW >> 1) + rowoff;
            const uint32_t baB = (uint32_t)((m0 + g + 8) * YROW >> 1) + rowoff;
#pragma unroll 2
            for (int ks = 0; ks < 14; ks++) {
                uint32_t a0 = yh32[baA + ks * 8 + t];
                uint32_t a2 = yh32[baA + ks * 8 + t + 4];
                uint32_t a1 = yh32[baB + ks * 8 + t];
                uint32_t a3 = yh32[baB + ks * 8 + t + 4];
#pragma unroll
                for (int nt = 0; nt < 4; nt++) {
                    const int n = n0 + nt * 8 + g;
                    uint32_t bb = (uint32_t)(n * YROW >> 1) + rowoff;
                    uint32_t b0 = yh32[bb + ks * 8 + t];
                    uint32_t b1 = yh32[bb + ks * 8 + t + 4];
                    MMA16816(c[nt], a0, a1, a2, a3, b0, b1);
                }
            }
        }

        float* dst = g_ytypart + (size_t)band * 4096;
#pragma unroll
        for (int nt = 0; nt < 4; nt++) {
            const int col = n0 + nt * 8 + 2 * t;
            *(float2*)&dst[(m0 + g) * 64 + col]     = make_float2(c[nt][0], c[nt][1]);
            *(float2*)&dst[(m0 + g + 8) * 64 + col] = make_float2(c[nt][2], c[nt][3]);
        }

        {
            const int oc = tid >> 2, q = tid & 3;
            float s = 0.f;
#pragma unroll
            for (int b2 = 0; b2 < 4; b2++) {
                const uint32_t base = (uint32_t)(oc * YROW >> 1) +
                                      (uint32_t)((band * 4 + b2) * 112) + q * 28;
#pragma unroll 7
                for (int k = 0; k < 28; k++) {
                    uint32_t v = yh32[base + k];
                    __nv_bfloat162 hh = *(__nv_bfloat162*)&v;
                    float2 f = __bfloat1622float2(hh);
                    s += f.x + f.y;
                }
            }
            s += __shfl_xor_sync(0xFFFFFFFFu, s, 1);
            s += __shfl_xor_sync(0xFFFFFFFFu, s, 2);
            if (q == 0) g_colpart[band * OCH + oc] = s;
        }
    }
}

// ======================================================================
// K3: reduce partials + exp_new/gfp. grid 37 x 256.
// ======================================================================
__global__ void k_reduce(const float* __restrict__ exp_avg,
                         float* __restrict__ dout)
{
    int e = blockIdx.x * 256 + threadIdx.x;
    if (e < 8192) {
        const float4* P = (const float4*)g_Cpart;
        float4 s = make_float4(0.f, 0.f, 0.f, 0.f);
#pragma unroll 5
        for (int b = 0; b < MB4; b++) {
            float4 v = P[(size_t)b * 8192 + e];
            s.x += v.x; s.y += v.y; s.z += v.z; s.w += v.w;
        }
        ((float4*)g_Cfin)[e] = s;
    } else if (e < 9216) {
        int i = e - 8192;
        const float4* P = (const float4*)g_ytypart;
        float4 s = make_float4(0.f, 0.f, 0.f, 0.f);
#pragma unroll 5
        for (int b = 0; b < MB4; b++) {
            float4 v = P[(size_t)b * 1024 + i];
            s.x += v.x; s.y += v.y; s.z += v.z; s.w += v.w;
        }
        ((float4*)g_ytyF)[i] = s;
    }

    if (blockIdx.x == 36) {
        __shared__ float sh[OCH];
        int t = threadIdx.x;
        if (t < OCH) {
            float cs = 0.f;
#pragma unroll 5
            for (int b = 0; b < MB4; b++) cs += g_colpart[b * OCH + t];
            float en = 0.99f * exp_avg[t] + (1.0f - 0.99f) * (cs / (float)NB);
            sh[t] = en;
            dout[OUT_OFF_EXP + t] = en;
        }
        __syncthreads();
        if (t < OCH) {
            float s = 0.f;
            for (int i = 0; i < OCH; i++) s += sh[i];
            float A = sh[t] / (s * (1.0f / (float)OCH));
            g_gfp[t] = 0.01f * tanhf(-0.01f * (A - 1.0f)) + 1.0f;
        }
    }
}

// ======================================================================
// K4: weight update.
// ======================================================================
__global__ void k_wupd(const float* __restrict__ W, float* __restrict__ dout)
{
    int idx = blockIdx.x * 256 + threadIdx.x;
    if (idx >= OCH * KTOT) return;
    int oc = idx / KTOT;
    int k = idx - oc * KTOT;
    float dot = 0.f;
#pragma unroll 8
    for (int b = 0; b < OCH; b++)
        dot += g_ytyF[oc * OCH + b] * W[b * KTOT + k];
    const float LRN = (float)(0.005 / 48400.0);
    float d = LRN * (g_Cfin[k * 64 + oc] - dot);
    float wn = fmaxf(W[idx] + d, 0.f);
    dout[OUT_OFF_W + idx] = wn * g_gfp[oc];
}

// ======================================================================
extern "C" void kernel_launch(void* const* d_in, const int* in_sizes, int n_in,
                              void* d_out, int out_size)
{
    const float* x  = (const float*)d_in[0];
    const float* W  = (const float*)d_in[1];
    const float* ea = (const float*)d_in[2];
    float* dout = (float*)d_out;

    const int hebb_smem = 2 * BSZ * 4;   // 59392 B
    cudaFuncSetAttribute(k_hebb_mma,
                         cudaFuncAttributeMaxDynamicSharedMemorySize, hebb_smem);

    k_cvt_x<<<(XSZ + 255) / 256, 256>>>(x);
    k_cvt_w<<<(OCH * KTOT + OCH * 440 + 255) / 256, 256>>>(W);
    dim3 g1(2, 220);
    k_conv_mma<<<g1, 224>>>(dout);
    dim3 g2(MB4, 5);
    k_hebb_mma<<<g2, 256, hebb_smem>>>();
    k_reduce<<<37, 256>>>(ea, dout);
    k_wupd<<<100, 256>>>(W, dout);
}

// round 14
// speedup vs baseline: 1.7484x; 1.0233x over previous
#include <cuda_runtime.h>
#include <cuda_bf16.h>
#include <cstdint>

// ---------------- problem constants ----------------
#define INS   224
#define NH    220
#define NB    48400
#define ICH   16
#define OCH   64
#define KTOT  400
#define XSZ   (ICH*INS*INS)      // 802816

#define OUT_OFF_W   (OCH*NB)
#define OUT_OFF_EXP (OUT_OFF_W + OCH*KTOT)

#define MB2   110                // hebb bands (2 image rows each)
#define YROW  49280              // g_yh per-oc size: 220 rows x 224 (pad 4 = 0)

// ---------------- scratch ----------------
__device__ __nv_bfloat16 g_xh[XSZ];
__device__ __nv_bfloat16 g_xl[XSZ];
__device__ __nv_bfloat16 g_xhs[XSZ];         // bf16(x[e+1])
__device__ __nv_bfloat16 g_xls[XSZ];         // lo(x[e+1])
__device__ uint32_t g_xq_h[XSZ];             // pack(hi x[e], hi x[e+220])
__device__ uint32_t g_xq_l[XSZ];
__device__ uint32_t g_xr_h[XSZ];             // pack(hi x[e], hi x[e+49276])
__device__ uint32_t g_xr_l[XSZ];
__device__ __nv_bfloat16 g_Wh[OCH * KTOT];
__device__ __nv_bfloat16 g_Wl[OCH * KTOT];
__device__ __nv_bfloat16 g_yh[OCH * YROW];
__device__ float g_Cpart[MB2 * 512 * OCH];   // 14.4MB
__device__ float g_ytypart[MB2 * OCH * OCH];
__device__ float g_colpart[MB2 * OCH];
__device__ float g_Cfin[512 * OCH];
__device__ float g_ytyF[OCH * OCH];
__device__ float g_gfp[OCH];

#define MMA16816(c, a0,a1,a2,a3, b0,b1) \
  asm volatile("mma.sync.aligned.m16n8k16.row.col.f32.bf16.bf16.f32 " \
    "{%0,%1,%2,%3},{%4,%5,%6,%7},{%8,%9},{%0,%1,%2,%3};" \
    : "+f"((c)[0]),"+f"((c)[1]),"+f"((c)[2]),"+f"((c)[3]) \
    : "r"(a0),"r"(a1),"r"(a2),"r"(a3),"r"(b0),"r"(b1))

#define LDSM4(r0,r1,r2,r3, saddr) \
  asm volatile("ldmatrix.sync.aligned.m8n8.x4.shared.b16 {%0,%1,%2,%3}, [%4];" \
    : "=r"(r0),"=r"(r1),"=r"(r2),"=r"(r3) : "r"(saddr))

#define CP_ASYNC4(saddr, gptr) \
  asm volatile("cp.async.ca.shared.global [%0], [%1], 4;" \
    :: "r"(saddr), "l"(gptr) : "memory")
#define CP_COMMIT()   asm volatile("cp.async.commit_group;" ::: "memory")
#define CP_WAIT_ALL() asm volatile("cp.async.wait_group 0;" ::: "memory")

__device__ __forceinline__ uint32_t smem_u32(const void* p) {
    return (uint32_t)__cvta_generic_to_shared(p);
}
__device__ __forceinline__ uint32_t pack_bf2(__nv_bfloat16 lo, __nv_bfloat16 hi) {
    unsigned short a = *(unsigned short*)&lo, b = *(unsigned short*)&hi;
    return (uint32_t)a | ((uint32_t)b << 16);
}

// ======================================================================
// K0a: x -> all bf16 pair arrays
// ======================================================================
__global__ void k_cvt_x(const float* __restrict__ x)
{
    int e = blockIdx.x * 256 + threadIdx.x;
    if (e >= XSZ) return;
    float v = x[e];
    __nv_bfloat16 h = __float2bfloat16(v);
    __nv_bfloat16 l = __float2bfloat16(v - __bfloat162float(h));
    g_xh[e] = h; g_xl[e] = l;

    float v1 = (e + 1 < XSZ) ? x[e + 1] : 0.f;
    __nv_bfloat16 h1 = __float2bfloat16(v1);
    g_xhs[e] = h1;
    g_xls[e] = __float2bfloat16(v1 - __bfloat162float(h1));

    float vq = (e + 220 < XSZ) ? x[e + 220] : 0.f;
    __nv_bfloat16 hq = __float2bfloat16(vq);
    __nv_bfloat16 lq = __float2bfloat16(vq - __bfloat162float(hq));
    g_xq_h[e] = pack_bf2(h, hq);
    g_xq_l[e] = pack_bf2(l, lq);

    float vr = (e + 49276 < XSZ) ? x[e + 49276] : 0.f;
    __nv_bfloat16 hr = __float2bfloat16(vr);
    __nv_bfloat16 lr = __float2bfloat16(vr - __bfloat162float(hr));
    g_xr_h[e] = pack_bf2(h, hr);
    g_xr_l[e] = pack_bf2(l, lr);
}

// ======================================================================
// K0b: W -> bf16 hi/lo ; zero g_yh row pads
// ======================================================================
__global__ void k_cvt_w(const float* __restrict__ W)
{
    int idx = blockIdx.x * 256 + threadIdx.x;
    if (idx < OCH * KTOT) {
        float v = W[idx];
        __nv_bfloat16 h = __float2bfloat16(v);
        g_Wh[idx] = h;
        g_Wl[idx] = __float2bfloat16(v - __bfloat162float(h));
    } else if (idx < OCH * KTOT + OCH * 220 * 2) {
        int p = idx - OCH * KTOT;
        int oc = p / 440, rem = p - oc * 440;
        int r = rem >> 1, half = rem & 1;
        uint32_t* yh32 = (uint32_t*)g_yh;
        yh32[((oc * YROW + r * 224 + 220) >> 1) + half] = 0u;
    }
}

// ======================================================================
// A pair-load for conv: element pair (kb, kb+1) at pixel column eb(+8).
// ======================================================================
__device__ __forceinline__ void loadpairs(int kb, int eb, int pxA,
    uint32_t& h0, uint32_t& h1, uint32_t& l0, uint32_t& l1)
{
    int q = kb / 5;
    int kj = kb - q * 5;
    int ic = q / 5;
    int e = q * 224 + ic * 49056 + eb + kj;
    if (kj == 4) {
        bool icx = (q - ic * 5) == 4;
        const uint32_t* ph = icx ? g_xr_h : g_xq_h;
        const uint32_t* pl = icx ? g_xr_l : g_xq_l;
        h0 = ph[e]; h1 = ph[e + 8];
        l0 = pl[e]; l1 = pl[e + 8];
    } else {
        int par = (pxA + kj) & 1;
        const uint32_t* ph = par ? (const uint32_t*)g_xhs : (const uint32_t*)g_xh;
        const uint32_t* pl = par ? (const uint32_t*)g_xls : (const uint32_t*)g_xl;
        int w0 = e >> 1;
        h0 = ph[w0]; h1 = ph[w0 + 4];
        l0 = pl[w0]; l1 = pl[w0 + 4];
    }
}

// ======================================================================
// K1: conv + inhibition, split-bf16 MMA, A direct-global, W via LDSM,
// W-chunks double-buffered with cp.async. (R13 verbatim)
// grid (2, 220), 224 thr (7 warps). Warp = 16 px x 64 oc.
// ======================================================================
#define WPITCH 20
#define WBUF   (64 * WPITCH)

__global__ void __launch_bounds__(224, 4)
k_conv_mma(float* __restrict__ dout)
{
    __shared__ uint32_t wsh[2 * WBUF];
    __shared__ uint32_t wsl[2 * WBUF];

    const int tid = threadIdx.x;
    const int w = tid >> 5, lane = tid & 31;
    const int g = lane >> 2, t = lane & 3;
    const int h = blockIdx.x;
    const int i = blockIdx.y;
    const int J0 = h * 108;
    const int pxA = (w << 4) + g;
    const int eb = i * 224 + J0 + pxA;

    const int nrow_off = ((lane >> 4) & 1) * 8 + (lane & 7);
    const int k_off = ((lane >> 3) & 1) * 4;
    const uint32_t wsh_s = smem_u32(wsh);
    const uint32_t wsl_s = smem_u32(wsl);
    const uint32_t* wh2g = (const uint32_t*)g_Wh;
    const uint32_t* wl2g = (const uint32_t*)g_Wl;

    float c[8][4];
#pragma unroll
    for (int nt = 0; nt < 8; nt++)
#pragma unroll
        for (int q = 0; q < 4; q++) c[nt][q] = 0.f;

    auto fillW = [&](int s, int buf) {
        const int nu = (s < 12) ? 16 : 8;
        const int base = s * 16;
        for (int idx = tid; idx < 64 * nu; idx += 224) {
            int row, u;
            if (nu == 16) { row = idx >> 4; u = idx & 15; }
            else          { row = idx >> 3; u = idx & 7;  }
            uint32_t so = (uint32_t)(buf * WBUF + row * WPITCH + u) * 4;
            CP_ASYNC4(wsh_s + so, wh2g + row * 200 + base + u);
            CP_ASYNC4(wsl_s + so, wl2g + row * 200 + base + u);
        }
    };

    fillW(0, 0);
    CP_COMMIT();

    for (int s = 0; s < 13; s++) {
        CP_WAIT_ALL();
        __syncthreads();
        if (s < 12) { fillW(s + 1, (s + 1) & 1); CP_COMMIT(); }

        const int k0s = s * 32;
        const int nks = (s < 12) ? 2 : 1;
        const uint32_t bufoff = (uint32_t)((s & 1) * WBUF) * 4;

        for (int ksl = 0; ksl < nks; ksl++) {
            const int kb0 = k0s + ksl * 16 + 2 * t;
            uint32_t ah0, ah1, al0, al1, ah2, ah3, al2, al3;
            loadpairs(kb0,     eb, pxA, ah0, ah1, al0, al1);
            loadpairs(kb0 + 8, eb, pxA, ah2, ah3, al2, al3);

            const uint32_t wbase = bufoff +
                ((uint32_t)(nrow_off * WPITCH + ksl * 8 + k_off)) * 4;
#pragma unroll
            for (int p = 0; p < 4; p++) {
                uint32_t bh0, bh1, bh2, bh3, bl0, bl1, bl2, bl3;
                const uint32_t off = wbase + (uint32_t)(p * 16 * WPITCH) * 4;
                LDSM4(bh0, bh1, bh2, bh3, wsh_s + off);
                LDSM4(bl0, bl1, bl2, bl3, wsl_s + off);
                MMA16816(c[2 * p],     ah0, ah1, ah2, ah3, bh0, bh1);
                MMA16816(c[2 * p],     al0, al1, al2, al3, bh0, bh1);
                MMA16816(c[2 * p],     ah0, ah1, ah2, ah3, bl0, bl1);
                MMA16816(c[2 * p + 1], ah0, ah1, ah2, ah3, bh2, bh3);
                MMA16816(c[2 * p + 1], al0, al1, al2, al3, bh2, bh3);
                MMA16816(c[2 * p + 1], ah0, ah1, ah2, ah3, bl2, bl3);
            }
        }
        __syncthreads();
    }

    // ---- inhibition + writeback ----
    float m0 = 0.f, m1 = 0.f;
#pragma unroll
    for (int nt = 0; nt < 8; nt++) {
        m0 = fmaxf(m0, fmaxf(c[nt][0], c[nt][1]));
        m1 = fmaxf(m1, fmaxf(c[nt][2], c[nt][3]));
    }
    m0 = fmaxf(m0, __shfl_xor_sync(0xFFFFFFFFu, m0, 1));
    m0 = fmaxf(m0, __shfl_xor_sync(0xFFFFFFFFu, m0, 2));
    m1 = fmaxf(m1, __shfl_xor_sync(0xFFFFFFFFu, m1, 1));
    m1 = fmaxf(m1, __shfl_xor_sync(0xFFFFFFFFu, m1, 2));
    const float inv0 = 1.f / (m0 + 1e-9f);
    const float inv1 = 1.f / (m1 + 1e-9f);

    const int pxg = i * NH + J0 + pxA;
    const int pyg = i * 224 + J0 + pxA;
#pragma unroll
    for (int nt = 0; nt < 8; nt++) {
        const int oc = nt * 8 + 2 * t;
        float v;
        v = fmaxf(c[nt][0], 0.f) * inv0; v = (v * v) * (v * v) * v;
        dout[(size_t)oc * NB + pxg] = v;
        g_yh[(size_t)oc * YROW + pyg] = __float2bfloat16(v);
        v = fmaxf(c[nt][1], 0.f) * inv0; v = (v * v) * (v * v) * v;
        dout[(size_t)(oc + 1) * NB + pxg] = v;
        g_yh[(size_t)(oc + 1) * YROW + pyg] = __float2bfloat16(v);
        v = fmaxf(c[nt][2], 0.f) * inv1; v = (v * v) * (v * v) * v;
        dout[(size_t)oc * NB + pxg + 8] = v;
        g_yh[(size_t)oc * YROW + pyg + 8] = __float2bfloat16(v);
        v = fmaxf(c[nt][3], 0.f) * inv1; v = (v * v) * (v * v) * v;
        dout[(size_t)(oc + 1) * NB + pxg + 8] = v;
        g_yh[(size_t)(oc + 1) * YROW + pyg + 8] = __float2bfloat16(v);
    }
}

// ======================================================================
// K2: fused Hebbian GEMMs. grid (110, 5), 256 thr, 59.4KB dyn smem.
//   kt 0..3 : y^T @ xf over 2 rows (A direct-global,
//             B double-buffered via cp.async + LDSM)
//   kt == 4 : y^T @ y + colsums over 2 rows (frag-direct global)
// ======================================================================
#define BPITCH 116
#define BSZ    (64 * BPITCH)       // 7424 u32 per buffer

extern __shared__ uint32_t s_B[];  // 2 * BSZ

__global__ void __launch_bounds__(256, 3)
k_hebb_mma()
{
    const int tid  = threadIdx.x;
    const int band = blockIdx.x;     // rows 2*band, 2*band+1
    const int kt   = blockIdx.y;
    const int w    = tid >> 5;
    const int lane = tid & 31;
    const int g    = lane >> 2;
    const int t    = lane & 3;

    const uint32_t* yh32 = (const uint32_t*)g_yh;

    if (kt < 4) {
        // ---------------- y^T @ xf ----------------
        const uint32_t* xh32  = (const uint32_t*)g_xh;
        const uint32_t* xhs32 = (const uint32_t*)g_xhs;

        int rA = kt * 128 + w * 16 + g;
        int rB = rA + 8;
        int rc0 = 0, rc1 = 0;
        const uint32_t *p0 = xh32, *p1 = xh32;
        if (rA < KTOT) {
            int ic = rA / 25, rem = rA - ic * 25;
            int ki = rem / 5, kj = rem - ki * 5;
            rc0 = ic * 50176 + ki * 224 + kj;
            if (kj & 1) p0 = xhs32;
        }
        if (rB < KTOT) {
            int ic = rB / 25, rem = rB - ic * 25;
            int ki = rem / 5, kj = rem - ki * 5;
            rc1 = ic * 50176 + ki * 224 + kj;
            if (kj & 1) p1 = xhs32;
        }

        const uint32_t bsm = smem_u32(s_B);
        const int nrow_off = ((lane >> 4) & 1) * 8 + (lane & 7);
        const int k_off = ((lane >> 3) & 1) * 4;

        // zero the pad words of both buffers (written once, stay zero)
        {
            int buf = tid >> 7, rem = tid & 127;
            int row = rem >> 1, p = rem & 1;
            s_B[buf * BSZ + row * BPITCH + 110 + p] = 0u;
        }

        auto fillB = [&](int ir, int buf) {
            for (int idx = tid; idx < 64 * 112; idx += 256) {
                int row = idx / 112, pc = idx - row * 112;
                if (pc < 110) {
                    uint32_t so = (uint32_t)(buf * BSZ + row * BPITCH + pc) * 4;
                    CP_ASYNC4(bsm + so, yh32 + ((row * YROW + ir * 224) >> 1) + pc);
                }
            }
        };

        float c[8][4];
#pragma unroll
        for (int n = 0; n < 8; n++)
#pragma unroll
            for (int q = 0; q < 4; q++) c[n][q] = 0.f;

        fillB(band * 2, 0);
        CP_COMMIT();

#pragma unroll
        for (int b2 = 0; b2 < 2; b2++) {
            const int ir = band * 2 + b2;
            CP_WAIT_ALL();
            __syncthreads();
            if (b2 < 1) { fillB(ir + 1, 1); CP_COMMIT(); }

            const uint32_t ba0 = (uint32_t)(rc0 + ir * 224) >> 1;
            const uint32_t ba1 = (uint32_t)(rc1 + ir * 224) >> 1;
            const uint32_t bufoff = (uint32_t)(b2 * BSZ) * 4;
#pragma unroll
            for (int ks = 0; ks < 14; ks++) {
                uint32_t a0 = p0[ba0 + ks * 8 + t];
                uint32_t a2 = p0[ba0 + ks * 8 + t + 4];
                uint32_t a1 = p1[ba1 + ks * 8 + t];
                uint32_t a3 = p1[ba1 + ks * 8 + t + 4];
#pragma unroll
                for (int p = 0; p < 4; p++) {
                    uint32_t b0, b1, b2r, b3;
                    uint32_t addr = bsm + bufoff +
                        (uint32_t)((p * 16 + nrow_off) * BPITCH + ks * 8 + k_off) * 4;
                    LDSM4(b0, b1, b2r, b3, addr);
                    MMA16816(c[2 * p],     a0, a1, a2, a3, b0, b1);
                    MMA16816(c[2 * p + 1], a0, a1, a2, a3, b2r, b3);
                }
            }
            __syncthreads();
        }

        float* dst = g_Cpart + ((size_t)band * 512 + kt * 128 + w * 16) * 64;
#pragma unroll
        for (int nt = 0; nt < 8; nt++) {
            *(float2*)&dst[(g)     * 64 + nt * 8 + 2 * t] = make_float2(c[nt][0], c[nt][1]);
            *(float2*)&dst[(g + 8) * 64 + nt * 8 + 2 * t] = make_float2(c[nt][2], c[nt][3]);
        }
    } else {
        // ---------------- y^T @ y + colsums ----------------
        const int m0 = (w & 3) * 16;
        const int n0 = (w >> 2) * 32;

        float c[4][4];
#pragma unroll
        for (int n = 0; n < 4; n++)
#pragma unroll
            for (int q = 0; q < 4; q++) c[n][q] = 0.f;

#pragma unroll
        for (int b2 = 0; b2 < 2; b2++) {
            const int ir = band * 2 + b2;
            const uint32_t rowoff = (uint32_t)(ir * 112);
            const uint32_t baA = (uint32_t)((m0 + g) * YROW >> 1) + rowoff;
            const uint32_t baB = (uint32_t)((m0 + g + 8) * YROW >> 1) + rowoff;
#pragma unroll 2
            for (int ks = 0; ks < 14; ks++) {
                uint32_t a0 = yh32[baA + ks * 8 + t];
                uint32_t a2 = yh32[baA + ks * 8 + t + 4];
                uint32_t a1 = yh32[baB + ks * 8 + t];
                uint32_t a3 = yh32[baB + ks * 8 + t + 4];
#pragma unroll
                for (int nt = 0; nt < 4; nt++) {
                    const int n = n0 + nt * 8 + g;
                    uint32_t bb = (uint32_t)(n * YROW >> 1) + rowoff;
                    uint32_t b0 = yh32[bb + ks * 8 + t];
                    uint32_t b1 = yh32[bb + ks * 8 + t + 4];
                    MMA16816(c[nt], a0, a1, a2, a3, b0, b1);
                }
            }
        }

        float* dst = g_ytypart + (size_t)band * 4096;
#pragma unroll
        for (int nt = 0; nt < 4; nt++) {
            const int col = n0 + nt * 8 + 2 * t;
            *(float2*)&dst[(m0 + g) * 64 + col]     = make_float2(c[nt][0], c[nt][1]);
            *(float2*)&dst[(m0 + g + 8) * 64 + col] = make_float2(c[nt][2], c[nt][3]);
        }

        {
            const int oc = tid >> 2, q = tid & 3;
            float s = 0.f;
#pragma unroll
            for (int b2 = 0; b2 < 2; b2++) {
                const uint32_t base = (uint32_t)(oc * YROW >> 1) +
                                      (uint32_t)((band * 2 + b2) * 112) + q * 28;
#pragma unroll 7
                for (int k = 0; k < 28; k++) {
                    uint32_t v = yh32[base + k];
                    __nv_bfloat162 hh = *(__nv_bfloat162*)&v;
                    float2 f = __bfloat1622float2(hh);
                    s += f.x + f.y;
                }
            }
            s += __shfl_xor_sync(0xFFFFFFFFu, s, 1);
            s += __shfl_xor_sync(0xFFFFFFFFu, s, 2);
            if (q == 0) g_colpart[band * OCH + oc] = s;
        }
    }
}

// ======================================================================
// K3: reduce partials + exp_new/gfp. grid 37 x 256.
// ======================================================================
__global__ void k_reduce(const float* __restrict__ exp_avg,
                         float* __restrict__ dout)
{
    int e = blockIdx.x * 256 + threadIdx.x;
    if (e < 8192) {
        const float4* P = (const float4*)g_Cpart;
        float4 s = make_float4(0.f, 0.f, 0.f, 0.f);
#pragma unroll 5
        for (int b = 0; b < MB2; b++) {
            float4 v = P[(size_t)b * 8192 + e];
            s.x += v.x; s.y += v.y; s.z += v.z; s.w += v.w;
        }
        ((float4*)g_Cfin)[e] = s;
    } else if (e < 9216) {
        int i = e - 8192;
        const float4* P = (const float4*)g_ytypart;
        float4 s = make_float4(0.f, 0.f, 0.f, 0.f);
#pragma unroll 5
        for (int b = 0; b < MB2; b++) {
            float4 v = P[(size_t)b * 1024 + i];
            s.x += v.x; s.y += v.y; s.z += v.z; s.w += v.w;
        }
        ((float4*)g_ytyF)[i] = s;
    }

    if (blockIdx.x == 36) {
        __shared__ float sh[OCH];
        int t = threadIdx.x;
        if (t < OCH) {
            float cs = 0.f;
#pragma unroll 5
            for (int b = 0; b < MB2; b++) cs += g_colpart[b * OCH + t];
            float en = 0.99f * exp_avg[t] + (1.0f - 0.99f) * (cs / (float)NB);
            sh[t] = en;
            dout[OUT_OFF_EXP + t] = en;
        }
        __syncthreads();
        if (t < OCH) {
            float s = 0.f;
            for (int i = 0; i < OCH; i++) s += sh[i];
            float A = sh[t] / (s * (1.0f / (float)OCH));
            g_gfp[t] = 0.01f * tanhf(-0.01f * (A - 1.0f)) + 1.0f;
        }
    }
}

// ======================================================================
// K4: weight update.
// ======================================================================
__global__ void k_wupd(const float* __restrict__ W, float* __restrict__ dout)
{
    int idx = blockIdx.x * 256 + threadIdx.x;
    if (idx >= OCH * KTOT) return;
    int oc = idx / KTOT;
    int k = idx - oc * KTOT;
    float dot = 0.f;
#pragma unroll 8
    for (int b = 0; b < OCH; b++)
        dot += g_ytyF[oc * OCH + b] * W[b * KTOT + k];
    const float LRN = (float)(0.005 / 48400.0);
    float d = LRN * (g_Cfin[k * 64 + oc] - dot);
    float wn = fmaxf(W[idx] + d, 0.f);
    dout[OUT_OFF_W + idx] = wn * g_gfp[oc];
}

// ======================================================================
extern "C" void kernel_launch(void* const* d_in, const int* in_sizes, int n_in,
                              void* d_out, int out_size)
{
    const float* x  = (const float*)d_in[0];
    const float* W  = (const float*)d_in[1];
    const float* ea = (const float*)d_in[2];
    float* dout = (float*)d_out;

    const int hebb_smem = 2 * BSZ * 4;   // 59392 B
    cudaFuncSetAttribute(k_hebb_mma,
                         cudaFuncAttributeMaxDynamicSharedMemorySize, hebb_smem);

    k_cvt_x<<<(XSZ + 255) / 256, 256>>>(x);
    k_cvt_w<<<(OCH * KTOT + OCH * 440 + 255) / 256, 256>>>(W);
    dim3 g1(2, 220);
    k_conv_mma<<<g1, 224>>>(dout);
    dim3 g2(MB2, 5);
    k_hebb_mma<<<g2, 256, hebb_smem>>>();
    k_reduce<<<37, 256>>>(ea, dout);
    k_wupd<<<100, 256>>>(W, dout);
}